// round 2
// baseline (speedup 1.0000x reference)
#include <cuda_runtime.h>

// ---------------- problem constants ----------------
#define S_   128
#define R_   256
#define CM_  256
#define CZ_  128
#define H_   8
#define CH_  32
#define HC_  256
#define NROW_ (S_*R_)   // 32768
#define NZ_   (R_*R_)   // 65536
#define EPS_  1e-5f
#define INF_  1e9f

// ---------------- scratch (static device globals; no allocation) ----------------
__device__ float g_mln[NROW_*CM_];   // LN(m)
__device__ float g_q  [NROW_*HC_];
__device__ float g_k  [NROW_*HC_];
__device__ float g_v  [NROW_*HC_];
__device__ float g_g  [NROW_*HC_];   // sigmoid gate
__device__ float g_og [NROW_*HC_];   // o * g
__device__ float g_zb [H_*NZ_];      // pair bias per head [H][R][R]

// ---------------- kernel 1: LayerNorm over m rows (C_M=256) ----------------
// grid = NROW_, block = 64, each thread handles 4 channels (float4)
__global__ void ln_m_kernel(const float* __restrict__ m,
                            const float* __restrict__ gam,
                            const float* __restrict__ bet) {
    const int row = blockIdx.x;
    const int t = threadIdx.x;   // 0..63
    const float4 x = ((const float4*)(m + (size_t)row * CM_))[t];
    float s = x.x + x.y + x.z + x.w;
    float q = x.x*x.x + x.y*x.y + x.z*x.z + x.w*x.w;
    #pragma unroll
    for (int o = 16; o > 0; o >>= 1) {
        s += __shfl_down_sync(0xffffffffu, s, o);
        q += __shfl_down_sync(0xffffffffu, q, o);
    }
    __shared__ float ss[2], sq[2];
    if ((t & 31) == 0) { ss[t >> 5] = s; sq[t >> 5] = q; }
    __syncthreads();
    const float mu  = (ss[0] + ss[1]) * (1.0f / CM_);
    const float var = (sq[0] + sq[1]) * (1.0f / CM_) - mu * mu;
    const float rs  = rsqrtf(var + EPS_);
    const float4 gv = ((const float4*)gam)[t];
    const float4 bv = ((const float4*)bet)[t];
    float4 y;
    y.x = (x.x - mu) * rs * gv.x + bv.x;
    y.y = (x.y - mu) * rs * gv.y + bv.y;
    y.z = (x.z - mu) * rs * gv.z + bv.z;
    y.w = (x.w - mu) * rs * gv.w + bv.w;
    ((float4*)(g_mln + (size_t)row * CM_))[t] = y;
}

// ---------------- kernel 2: pair bias zb[h][i][j] = (LN(z[i,j,:]) @ w_z)[h] ----------------
// grid = NZ_, block = 128 (one thread per z channel)
__global__ void zb_kernel(const float* __restrict__ z,
                          const float* __restrict__ gam,
                          const float* __restrict__ bet,
                          const float* __restrict__ w_z) {
    const int row = blockIdx.x;     // i*R + j
    const int t = threadIdx.x;      // 0..127
    const float x = z[(size_t)row * CZ_ + t];
    float s = x, q = x * x;
    #pragma unroll
    for (int o = 16; o > 0; o >>= 1) {
        s += __shfl_down_sync(0xffffffffu, s, o);
        q += __shfl_down_sync(0xffffffffu, q, o);
    }
    __shared__ float ss[4], sq[4];
    if ((t & 31) == 0) { ss[t >> 5] = s; sq[t >> 5] = q; }
    __syncthreads();
    const float mu  = (ss[0]+ss[1]+ss[2]+ss[3]) * (1.0f / CZ_);
    const float var = (sq[0]+sq[1]+sq[2]+sq[3]) * (1.0f / CZ_) - mu * mu;
    const float rs  = rsqrtf(var + EPS_);
    const float xn  = (x - mu) * rs * gam[t] + bet[t];
    float p[H_];
    #pragma unroll
    for (int h = 0; h < H_; h++) p[h] = xn * w_z[t * H_ + h];
    #pragma unroll
    for (int o = 16; o > 0; o >>= 1) {
        #pragma unroll
        for (int h = 0; h < H_; h++) p[h] += __shfl_down_sync(0xffffffffu, p[h], o);
    }
    __shared__ float pr[4][H_];
    if ((t & 31) == 0) {
        #pragma unroll
        for (int h = 0; h < H_; h++) pr[t >> 5][h] = p[h];
    }
    __syncthreads();
    if (t < H_) {
        const float r = pr[0][t] + pr[1][t] + pr[2][t] + pr[3][t];
        g_zb[(size_t)t * NZ_ + row] = r;
    }
}

// ---------------- kernel 3: tiled fp32 GEMM C[M,256] = A[M,256] @ B[256,256] (+epilogue) ----
// MODE 0: *= 1/sqrt(32) (q)   MODE 1: plain (k,v)
// MODE 2: sigmoid(x + bias)   (g)     MODE 3: x + bias (output)
// BM=BN=64, BK=16, 256 threads, 4x4 micro-tile
template <int MODE>
__global__ void __launch_bounds__(256) gemm64(const float* __restrict__ A,
                                              const float* __restrict__ B,
                                              const float* __restrict__ bias,
                                              float* __restrict__ Cout) {
    __shared__ float As[64][17];   // [mrow][k] padded
    __shared__ float Bs[16][64];   // [k][ncol]
    const int t = threadIdx.x;
    const int ty = t >> 4, tx = t & 15;
    const int row0 = blockIdx.y * 64;
    const int col0 = blockIdx.x * 64;
    const int arow = t >> 2, ac4 = t & 3;
    const int brow = t >> 4, bc4 = t & 15;

    float acc[4][4];
    #pragma unroll
    for (int i = 0; i < 4; i++)
        #pragma unroll
        for (int j = 0; j < 4; j++) acc[i][j] = 0.0f;

    for (int kt = 0; kt < 256 / 16; kt++) {
        const float4 av = *(const float4*)(A + (size_t)(row0 + arow) * 256 + kt * 16 + ac4 * 4);
        As[arow][ac4*4+0] = av.x; As[arow][ac4*4+1] = av.y;
        As[arow][ac4*4+2] = av.z; As[arow][ac4*4+3] = av.w;
        const float4 bv = *(const float4*)(B + (size_t)(kt * 16 + brow) * 256 + col0 + bc4 * 4);
        *(float4*)&Bs[brow][bc4 * 4] = bv;
        __syncthreads();
        #pragma unroll
        for (int kk = 0; kk < 16; kk++) {
            float a0 = As[ty*4+0][kk], a1 = As[ty*4+1][kk];
            float a2 = As[ty*4+2][kk], a3 = As[ty*4+3][kk];
            const float4 b4 = *(const float4*)&Bs[kk][tx * 4];
            acc[0][0] += a0*b4.x; acc[0][1] += a0*b4.y; acc[0][2] += a0*b4.z; acc[0][3] += a0*b4.w;
            acc[1][0] += a1*b4.x; acc[1][1] += a1*b4.y; acc[1][2] += a1*b4.z; acc[1][3] += a1*b4.w;
            acc[2][0] += a2*b4.x; acc[2][1] += a2*b4.y; acc[2][2] += a2*b4.z; acc[2][3] += a2*b4.w;
            acc[3][0] += a3*b4.x; acc[3][1] += a3*b4.y; acc[3][2] += a3*b4.z; acc[3][3] += a3*b4.w;
        }
        __syncthreads();
    }
    #pragma unroll
    for (int i = 0; i < 4; i++) {
        const int r = row0 + ty * 4 + i;
        const int c = col0 + tx * 4;
        float4 v;
        v.x = acc[i][0]; v.y = acc[i][1]; v.z = acc[i][2]; v.w = acc[i][3];
        if (MODE == 0) {
            const float sc = 0.17677669529663688f;   // 1/sqrt(32)
            v.x *= sc; v.y *= sc; v.z *= sc; v.w *= sc;
        } else if (MODE == 2) {
            v.x = 1.0f / (1.0f + __expf(-(v.x + bias[c+0])));
            v.y = 1.0f / (1.0f + __expf(-(v.y + bias[c+1])));
            v.z = 1.0f / (1.0f + __expf(-(v.z + bias[c+2])));
            v.w = 1.0f / (1.0f + __expf(-(v.w + bias[c+3])));
        } else if (MODE == 3) {
            v.x += bias[c+0]; v.y += bias[c+1]; v.z += bias[c+2]; v.w += bias[c+3];
        }
        *(float4*)(Cout + (size_t)r * 256 + c) = v;
    }
}

// ---------------- kernel 4: fused attention per (s,h) with online softmax ----------------
// grid = (H, S); block = 256 (one thread per query row r). o*g written to g_og.
__global__ void __launch_bounds__(256) attn_kernel(const float* __restrict__ mask) {
    const int h = blockIdx.x;
    const int s = blockIdx.y;
    const int t = threadIdx.x;                   // query row r
    __shared__ float ks[16][32];
    __shared__ float vs[16][32];
    __shared__ float zbs[256][17];               // padded: conflict-free row reads
    __shared__ float mb[256];

    // per-thread q row (already scaled by 1/sqrt(C))
    float qv[32];
    {
        const float* qp = g_q + ((size_t)(s * R_ + t)) * HC_ + h * CH_;
        #pragma unroll
        for (int i = 0; i < 8; i++) {
            const float4 f = *(const float4*)(qp + i * 4);
            qv[i*4+0] = f.x; qv[i*4+1] = f.y; qv[i*4+2] = f.z; qv[i*4+3] = f.w;
        }
    }
    mb[t] = INF_ * (mask[(size_t)s * R_ + t] - 1.0f);

    float acc[32];
    #pragma unroll
    for (int c = 0; c < 32; c++) acc[c] = 0.0f;
    float mrun = -3.0e38f, lrun = 0.0f;

    const float* zbh = g_zb + (size_t)h * NZ_;

    for (int jc = 0; jc < 16; jc++) {            // 16 chunks of 16 keys
        const int j0 = jc * 16;
        __syncthreads();                         // protect smem reuse
        if (t < 128) {
            const int rr = t >> 3, c4 = t & 7;
            const float4 f = *(const float4*)(g_k + ((size_t)(s * R_ + j0 + rr)) * HC_ + h * CH_ + c4 * 4);
            *(float4*)&ks[rr][c4 * 4] = f;
        } else {
            const int t2 = t - 128;
            const int rr = t2 >> 3, c4 = t2 & 7;
            const float4 f = *(const float4*)(g_v + ((size_t)(s * R_ + j0 + rr)) * HC_ + h * CH_ + c4 * 4);
            *(float4*)&vs[rr][c4 * 4] = f;
        }
        #pragma unroll
        for (int it = 0; it < 4; it++) {         // 256x16 zb tile, coalesced
            const int flat = it * 256 + t;
            const int rr = flat >> 2, c4 = flat & 3;
            const float4 f = *(const float4*)(zbh + (size_t)rr * R_ + j0 + c4 * 4);
            zbs[rr][c4*4+0] = f.x; zbs[rr][c4*4+1] = f.y;
            zbs[rr][c4*4+2] = f.z; zbs[rr][c4*4+3] = f.w;
        }
        __syncthreads();

        #pragma unroll
        for (int jj = 0; jj < 16; jj++) {
            float d0 = 0.f, d1 = 0.f, d2 = 0.f, d3 = 0.f;
            {
                const float4 k0 = *(const float4*)&ks[jj][0];
                const float4 k1 = *(const float4*)&ks[jj][4];
                const float4 k2 = *(const float4*)&ks[jj][8];
                const float4 k3 = *(const float4*)&ks[jj][12];
                const float4 k4 = *(const float4*)&ks[jj][16];
                const float4 k5 = *(const float4*)&ks[jj][20];
                const float4 k6 = *(const float4*)&ks[jj][24];
                const float4 k7 = *(const float4*)&ks[jj][28];
                d0 += qv[0]*k0.x + qv[1]*k0.y + qv[2]*k0.z + qv[3]*k0.w;
                d1 += qv[4]*k1.x + qv[5]*k1.y + qv[6]*k1.z + qv[7]*k1.w;
                d2 += qv[8]*k2.x + qv[9]*k2.y + qv[10]*k2.z + qv[11]*k2.w;
                d3 += qv[12]*k3.x + qv[13]*k3.y + qv[14]*k3.z + qv[15]*k3.w;
                d0 += qv[16]*k4.x + qv[17]*k4.y + qv[18]*k4.z + qv[19]*k4.w;
                d1 += qv[20]*k5.x + qv[21]*k5.y + qv[22]*k5.z + qv[23]*k5.w;
                d2 += qv[24]*k6.x + qv[25]*k6.y + qv[26]*k6.z + qv[27]*k6.w;
                d3 += qv[28]*k7.x + qv[29]*k7.y + qv[30]*k7.z + qv[31]*k7.w;
            }
            const float logit = (d0 + d1) + (d2 + d3) + mb[j0 + jj] + zbs[t][jj];
            if (logit > mrun) {
                const float sc = __expf(mrun - logit);
                lrun *= sc;
                #pragma unroll
                for (int c = 0; c < 32; c++) acc[c] *= sc;
                mrun = logit;
            }
            const float p = __expf(logit - mrun);
            lrun += p;
            #pragma unroll
            for (int i = 0; i < 8; i++) {
                const float4 vv = *(const float4*)&vs[jj][i * 4];
                acc[i*4+0] += p * vv.x;
                acc[i*4+1] += p * vv.y;
                acc[i*4+2] += p * vv.z;
                acc[i*4+3] += p * vv.w;
            }
        }
    }
    const float inv = 1.0f / lrun;
    const float* gp = g_g  + ((size_t)(s * R_ + t)) * HC_ + h * CH_;
    float*       op = g_og + ((size_t)(s * R_ + t)) * HC_ + h * CH_;
    #pragma unroll
    for (int i = 0; i < 8; i++) {
        const float4 gf = *(const float4*)(gp + i * 4);
        float4 of;
        of.x = acc[i*4+0] * inv * gf.x;
        of.y = acc[i*4+1] * inv * gf.y;
        of.z = acc[i*4+2] * inv * gf.z;
        of.w = acc[i*4+3] * inv * gf.w;
        *(float4*)(op + i * 4) = of;
    }
}

// ---------------- launch ----------------
extern "C" void kernel_launch(void* const* d_in, const int* in_sizes, int n_in,
                              void* d_out, int out_size) {
    const float* m      = (const float*)d_in[0];
    const float* z      = (const float*)d_in[1];
    const float* mask   = (const float*)d_in[2];
    const float* ln_m_g = (const float*)d_in[3];
    const float* ln_m_b = (const float*)d_in[4];
    const float* ln_z_g = (const float*)d_in[5];
    const float* ln_z_b = (const float*)d_in[6];
    const float* w_z    = (const float*)d_in[7];
    const float* wq     = (const float*)d_in[8];
    const float* wk     = (const float*)d_in[9];
    const float* wv     = (const float*)d_in[10];
    const float* wg     = (const float*)d_in[11];
    const float* bg     = (const float*)d_in[12];
    const float* wo     = (const float*)d_in[13];
    const float* bo     = (const float*)d_in[14];
    float* out = (float*)d_out;

    float *p_mln, *p_q, *p_k, *p_v, *p_g, *p_og;
    cudaGetSymbolAddress((void**)&p_mln, g_mln);
    cudaGetSymbolAddress((void**)&p_q,   g_q);
    cudaGetSymbolAddress((void**)&p_k,   g_k);
    cudaGetSymbolAddress((void**)&p_v,   g_v);
    cudaGetSymbolAddress((void**)&p_g,   g_g);
    cudaGetSymbolAddress((void**)&p_og,  g_og);

    ln_m_kernel<<<NROW_, 64>>>(m, ln_m_g, ln_m_b);
    zb_kernel<<<NZ_, 128>>>(z, ln_z_g, ln_z_b, w_z);

    const dim3 gg(4, NROW_ / 64);
    gemm64<0><<<gg, 256>>>(p_mln, wq, nullptr, p_q);
    gemm64<1><<<gg, 256>>>(p_mln, wk, nullptr, p_k);
    gemm64<1><<<gg, 256>>>(p_mln, wv, nullptr, p_v);
    gemm64<2><<<gg, 256>>>(p_mln, wg, bg,      p_g);

    attn_kernel<<<dim3(H_, S_), 256>>>(mask);

    gemm64<3><<<gg, 256>>>(p_og, wo, bo, out);
}

// round 3
// speedup vs baseline: 1.1491x; 1.1491x over previous
#include <cuda_runtime.h>

// ---------------- problem constants ----------------
#define S_   128
#define R_   256
#define CM_  256
#define CZ_  128
#define H_   8
#define CH_  32
#define HC_  256
#define NROW_ (S_*R_)   // 32768
#define NZ_   (R_*R_)   // 65536
#define EPS_  1e-5f
#define INF_  1e9f

// ---------------- scratch (static device globals; no allocation) ----------------
__device__ float g_mln[NROW_*CM_];   // LN(m)
__device__ float g_q  [NROW_*HC_];
__device__ float g_k  [NROW_*HC_];
__device__ float g_v  [NROW_*HC_];
__device__ float g_g  [NROW_*HC_];   // sigmoid gate
__device__ float g_og [NROW_*HC_];   // o * g
__device__ float g_zb [H_*NZ_];      // pair bias per head [H][R][R]

// ---------------- kernel 1: LayerNorm over m rows (C_M=256) ----------------
__global__ void ln_m_kernel(const float* __restrict__ m,
                            const float* __restrict__ gam,
                            const float* __restrict__ bet) {
    const int row = blockIdx.x;
    const int t = threadIdx.x;   // 0..63
    const float4 x = ((const float4*)(m + (size_t)row * CM_))[t];
    float s = x.x + x.y + x.z + x.w;
    float q = x.x*x.x + x.y*x.y + x.z*x.z + x.w*x.w;
    #pragma unroll
    for (int o = 16; o > 0; o >>= 1) {
        s += __shfl_down_sync(0xffffffffu, s, o);
        q += __shfl_down_sync(0xffffffffu, q, o);
    }
    __shared__ float ss[2], sq[2];
    if ((t & 31) == 0) { ss[t >> 5] = s; sq[t >> 5] = q; }
    __syncthreads();
    const float mu  = (ss[0] + ss[1]) * (1.0f / CM_);
    const float var = (sq[0] + sq[1]) * (1.0f / CM_) - mu * mu;
    const float rs  = rsqrtf(var + EPS_);
    const float4 gv = ((const float4*)gam)[t];
    const float4 bv = ((const float4*)bet)[t];
    float4 y;
    y.x = (x.x - mu) * rs * gv.x + bv.x;
    y.y = (x.y - mu) * rs * gv.y + bv.y;
    y.z = (x.z - mu) * rs * gv.z + bv.z;
    y.w = (x.w - mu) * rs * gv.w + bv.w;
    ((float4*)(g_mln + (size_t)row * CM_))[t] = y;
}

// ---------------- kernel 2: pair bias, one warp per z-row ----------------
// block = 256 (8 warps -> 8 rows), grid = NZ_/8
__global__ void __launch_bounds__(256) zb_kernel(const float* __restrict__ z,
                          const float* __restrict__ gam,
                          const float* __restrict__ bet,
                          const float* __restrict__ w_z) {
    const int t = threadIdx.x;
    const int w = t >> 5, l = t & 31;
    const int row0 = blockIdx.x * 8;
    const int row = row0 + w;
    __shared__ float outp[8][8];   // [local row][head]

    const float* zr = z + (size_t)row * CZ_;
    float x0 = zr[l], x1 = zr[l + 32], x2 = zr[l + 64], x3 = zr[l + 96];
    float s = x0 + x1 + x2 + x3;
    float q = x0*x0 + x1*x1 + x2*x2 + x3*x3;
    #pragma unroll
    for (int o = 16; o > 0; o >>= 1) {
        s += __shfl_xor_sync(0xffffffffu, s, o);
        q += __shfl_xor_sync(0xffffffffu, q, o);
    }
    const float mu  = s * (1.0f / CZ_);
    const float var = q * (1.0f / CZ_) - mu * mu;
    const float rs  = rsqrtf(var + EPS_);
    float xn[4];
    xn[0] = (x0 - mu) * rs * __ldg(gam + l)      + __ldg(bet + l);
    xn[1] = (x1 - mu) * rs * __ldg(gam + l + 32) + __ldg(bet + l + 32);
    xn[2] = (x2 - mu) * rs * __ldg(gam + l + 64) + __ldg(bet + l + 64);
    xn[3] = (x3 - mu) * rs * __ldg(gam + l + 96) + __ldg(bet + l + 96);

    float p[H_];
    #pragma unroll
    for (int h = 0; h < H_; h++) p[h] = 0.0f;
    #pragma unroll
    for (int i = 0; i < 4; i++) {
        const int c = l + 32 * i;
        #pragma unroll
        for (int h = 0; h < H_; h++) p[h] += xn[i] * __ldg(w_z + c * H_ + h);
    }
    #pragma unroll
    for (int o = 16; o > 0; o >>= 1) {
        #pragma unroll
        for (int h = 0; h < H_; h++) p[h] += __shfl_xor_sync(0xffffffffu, p[h], o);
    }
    if (l == 0) {
        #pragma unroll
        for (int h = 0; h < H_; h++) outp[w][h] = p[h];
    }
    __syncthreads();
    if (t < 64) {
        const int h = t >> 3, j = t & 7;
        g_zb[(size_t)h * NZ_ + row0 + j] = outp[j][h];
    }
}

// ---------------- kernel 3: tiled fp32 GEMM C[M,256] = A[M,256] @ B[256,256] ----
// BM=128, BN=128, BK=16, 256 threads, 8x8 micro-tile, A transposed in smem.
// MODE 0: *= 1/sqrt(32) (q)  1: plain (k,v)  2: sigmoid(x+bias) (g)  3: x+bias (out)
template <int MODE>
__global__ void __launch_bounds__(256, 2) gemm128(const float* __restrict__ A,
                                                  const float* __restrict__ B,
                                                  const float* __restrict__ bias,
                                                  float* __restrict__ Cout) {
    __shared__ float As[16][128];   // [k][m]
    __shared__ float Bs[16][128];   // [k][n]
    const int t = threadIdx.x;
    const int tx = t & 15;          // n block (8 cols each)
    const int ty = t >> 4;          // m block (8 rows each)
    const int row0 = blockIdx.y * 128;
    const int col0 = blockIdx.x * 128;
    const int arow = t >> 1, ak = (t & 1) * 8;
    const int brow = t >> 4, bcol = (t & 15) * 8;

    float acc[8][8];
    #pragma unroll
    for (int i = 0; i < 8; i++)
        #pragma unroll
        for (int j = 0; j < 8; j++) acc[i][j] = 0.0f;

    const float* Aptr = A + (size_t)(row0 + arow) * CM_ + ak;
    const float* Bptr = B + (size_t)brow * HC_ + col0 + bcol;

    for (int kt = 0; kt < CM_ / 16; kt++) {
        const float4 a0 = *(const float4*)(Aptr + kt * 16);
        const float4 a1 = *(const float4*)(Aptr + kt * 16 + 4);
        const float4 b0 = *(const float4*)(Bptr + (size_t)kt * 16 * HC_);
        const float4 b1 = *(const float4*)(Bptr + (size_t)kt * 16 * HC_ + 4);
        As[ak+0][arow] = a0.x; As[ak+1][arow] = a0.y;
        As[ak+2][arow] = a0.z; As[ak+3][arow] = a0.w;
        As[ak+4][arow] = a1.x; As[ak+5][arow] = a1.y;
        As[ak+6][arow] = a1.z; As[ak+7][arow] = a1.w;
        *(float4*)&Bs[brow][bcol]     = b0;
        *(float4*)&Bs[brow][bcol + 4] = b1;
        __syncthreads();
        #pragma unroll
        for (int kk = 0; kk < 16; kk++) {
            float a[8], b[8];
            *(float4*)&a[0] = *(const float4*)&As[kk][ty * 8];
            *(float4*)&a[4] = *(const float4*)&As[kk][ty * 8 + 4];
            *(float4*)&b[0] = *(const float4*)&Bs[kk][tx * 8];
            *(float4*)&b[4] = *(const float4*)&Bs[kk][tx * 8 + 4];
            #pragma unroll
            for (int i = 0; i < 8; i++)
                #pragma unroll
                for (int j = 0; j < 8; j++)
                    acc[i][j] += a[i] * b[j];
        }
        __syncthreads();
    }

    #pragma unroll
    for (int i = 0; i < 8; i++) {
        const int r = row0 + ty * 8 + i;
        float* crow = Cout + (size_t)r * HC_ + col0 + tx * 8;
        #pragma unroll
        for (int jq = 0; jq < 2; jq++) {
            const int c = col0 + tx * 8 + jq * 4;
            float4 v;
            v.x = acc[i][jq*4+0]; v.y = acc[i][jq*4+1];
            v.z = acc[i][jq*4+2]; v.w = acc[i][jq*4+3];
            if (MODE == 0) {
                const float sc = 0.17677669529663688f;   // 1/sqrt(32)
                v.x *= sc; v.y *= sc; v.z *= sc; v.w *= sc;
            } else if (MODE == 2) {
                v.x = 1.0f / (1.0f + __expf(-(v.x + bias[c+0])));
                v.y = 1.0f / (1.0f + __expf(-(v.y + bias[c+1])));
                v.z = 1.0f / (1.0f + __expf(-(v.z + bias[c+2])));
                v.w = 1.0f / (1.0f + __expf(-(v.w + bias[c+3])));
            } else if (MODE == 3) {
                v.x += bias[c+0]; v.y += bias[c+1];
                v.z += bias[c+2]; v.w += bias[c+3];
            }
            *(float4*)(crow + jq * 4) = v;
        }
    }
}

// ---------------- kernel 4: fused attention, chunked online softmax ----------------
// grid = (H, S); block = 256 (one thread per query row). o*g written to g_og.
__global__ void __launch_bounds__(256, 2) attn_kernel(const float* __restrict__ mask) {
    const int h = blockIdx.x;
    const int s = blockIdx.y;
    const int t = threadIdx.x;                   // query row
    __shared__ float ks[16][32];
    __shared__ float vs[16][32];
    __shared__ float mb[256];

    float qv[32];
    {
        const float* qp = g_q + ((size_t)(s * R_ + t)) * HC_ + h * CH_;
        #pragma unroll
        for (int i = 0; i < 8; i++) {
            const float4 f = *(const float4*)(qp + i * 4);
            qv[i*4+0] = f.x; qv[i*4+1] = f.y; qv[i*4+2] = f.z; qv[i*4+3] = f.w;
        }
    }
    mb[t] = INF_ * (mask[(size_t)s * R_ + t] - 1.0f);

    float acc[32];
    #pragma unroll
    for (int c = 0; c < 32; c++) acc[c] = 0.0f;
    float mrun = -3.0e38f, lrun = 0.0f;

    const float* zbrow = g_zb + (size_t)h * NZ_ + (size_t)t * R_;  // this query's bias row

    for (int jc = 0; jc < 16; jc++) {            // 16 chunks of 16 keys
        const int j0 = jc * 16;
        __syncthreads();
        if (t < 128) {
            const int rr = t >> 3, c4 = t & 7;
            const float4 f = *(const float4*)(g_k + ((size_t)(s * R_ + j0 + rr)) * HC_ + h * CH_ + c4 * 4);
            *(float4*)&ks[rr][c4 * 4] = f;
        } else {
            const int t2 = t - 128;
            const int rr = t2 >> 3, c4 = t2 & 7;
            const float4 f = *(const float4*)(g_v + ((size_t)(s * R_ + j0 + rr)) * HC_ + h * CH_ + c4 * 4);
            *(float4*)&vs[rr][c4 * 4] = f;
        }
        __syncthreads();

        // logits for 16 keys in registers (start from pair bias)
        float l[16];
        #pragma unroll
        for (int iq = 0; iq < 4; iq++) {
            const float4 f = *(const float4*)(zbrow + j0 + iq * 4);
            l[iq*4+0] = f.x; l[iq*4+1] = f.y; l[iq*4+2] = f.z; l[iq*4+3] = f.w;
        }
        #pragma unroll
        for (int jj = 0; jj < 16; jj++) {
            float d0 = 0.f, d1 = 0.f, d2 = 0.f, d3 = 0.f;
            const float4 k0 = *(const float4*)&ks[jj][0];
            const float4 k1 = *(const float4*)&ks[jj][4];
            const float4 k2 = *(const float4*)&ks[jj][8];
            const float4 k3 = *(const float4*)&ks[jj][12];
            const float4 k4 = *(const float4*)&ks[jj][16];
            const float4 k5 = *(const float4*)&ks[jj][20];
            const float4 k6 = *(const float4*)&ks[jj][24];
            const float4 k7 = *(const float4*)&ks[jj][28];
            d0 += qv[0]*k0.x + qv[1]*k0.y + qv[2]*k0.z + qv[3]*k0.w;
            d1 += qv[4]*k1.x + qv[5]*k1.y + qv[6]*k1.z + qv[7]*k1.w;
            d2 += qv[8]*k2.x + qv[9]*k2.y + qv[10]*k2.z + qv[11]*k2.w;
            d3 += qv[12]*k3.x + qv[13]*k3.y + qv[14]*k3.z + qv[15]*k3.w;
            d0 += qv[16]*k4.x + qv[17]*k4.y + qv[18]*k4.z + qv[19]*k4.w;
            d1 += qv[20]*k5.x + qv[21]*k5.y + qv[22]*k5.z + qv[23]*k5.w;
            d2 += qv[24]*k6.x + qv[25]*k6.y + qv[26]*k6.z + qv[27]*k6.w;
            d3 += qv[28]*k7.x + qv[29]*k7.y + qv[30]*k7.z + qv[31]*k7.w;
            l[jj] += (d0 + d1) + (d2 + d3) + mb[j0 + jj];
        }
        // chunk max + single rescale
        float cmax = l[0];
        #pragma unroll
        for (int jj = 1; jj < 16; jj++) cmax = fmaxf(cmax, l[jj]);
        if (cmax > mrun) {
            const float sc = __expf(mrun - cmax);
            lrun *= sc;
            #pragma unroll
            for (int c = 0; c < 32; c++) acc[c] *= sc;
            mrun = cmax;
        }
        #pragma unroll
        for (int jj = 0; jj < 16; jj++) {
            const float p = __expf(l[jj] - mrun);
            lrun += p;
            #pragma unroll
            for (int i = 0; i < 8; i++) {
                const float4 vv = *(const float4*)&vs[jj][i * 4];
                acc[i*4+0] += p * vv.x;
                acc[i*4+1] += p * vv.y;
                acc[i*4+2] += p * vv.z;
                acc[i*4+3] += p * vv.w;
            }
        }
    }
    const float inv = 1.0f / lrun;
    const float* gp = g_g  + ((size_t)(s * R_ + t)) * HC_ + h * CH_;
    float*       op = g_og + ((size_t)(s * R_ + t)) * HC_ + h * CH_;
    #pragma unroll
    for (int i = 0; i < 8; i++) {
        const float4 gf = *(const float4*)(gp + i * 4);
        float4 of;
        of.x = acc[i*4+0] * inv * gf.x;
        of.y = acc[i*4+1] * inv * gf.y;
        of.z = acc[i*4+2] * inv * gf.z;
        of.w = acc[i*4+3] * inv * gf.w;
        *(float4*)(op + i * 4) = of;
    }
}

// ---------------- launch ----------------
extern "C" void kernel_launch(void* const* d_in, const int* in_sizes, int n_in,
                              void* d_out, int out_size) {
    const float* m      = (const float*)d_in[0];
    const float* z      = (const float*)d_in[1];
    const float* mask   = (const float*)d_in[2];
    const float* ln_m_g = (const float*)d_in[3];
    const float* ln_m_b = (const float*)d_in[4];
    const float* ln_z_g = (const float*)d_in[5];
    const float* ln_z_b = (const float*)d_in[6];
    const float* w_z    = (const float*)d_in[7];
    const float* wq     = (const float*)d_in[8];
    const float* wk     = (const float*)d_in[9];
    const float* wv     = (const float*)d_in[10];
    const float* wg     = (const float*)d_in[11];
    const float* bg     = (const float*)d_in[12];
    const float* wo     = (const float*)d_in[13];
    const float* bo     = (const float*)d_in[14];
    float* out = (float*)d_out;

    float *p_mln, *p_q, *p_k, *p_v, *p_g, *p_og;
    cudaGetSymbolAddress((void**)&p_mln, g_mln);
    cudaGetSymbolAddress((void**)&p_q,   g_q);
    cudaGetSymbolAddress((void**)&p_k,   g_k);
    cudaGetSymbolAddress((void**)&p_v,   g_v);
    cudaGetSymbolAddress((void**)&p_g,   g_g);
    cudaGetSymbolAddress((void**)&p_og,  g_og);

    ln_m_kernel<<<NROW_, 64>>>(m, ln_m_g, ln_m_b);
    zb_kernel<<<NZ_ / 8, 256>>>(z, ln_z_g, ln_z_b, w_z);

    const dim3 gg(2, NROW_ / 128);
    gemm128<0><<<gg, 256>>>(p_mln, wq, nullptr, p_q);
    gemm128<1><<<gg, 256>>>(p_mln, wk, nullptr, p_k);
    gemm128<1><<<gg, 256>>>(p_mln, wv, nullptr, p_v);
    gemm128<2><<<gg, 256>>>(p_mln, wg, bg,      p_g);

    attn_kernel<<<dim3(H_, S_), 256>>>(mask);

    gemm128<3><<<gg, 256>>>(p_og, wo, bo, out);
}

// round 4
// speedup vs baseline: 1.4443x; 1.2569x over previous
#include <cuda_runtime.h>
#include <cuda_bf16.h>
#include <cstdint>

// ---------------- problem constants ----------------
#define S_   128
#define R_   256
#define CM_  256
#define CZ_  128
#define H_   8
#define CH_  32
#define HC_  256
#define NROW_ (S_*R_)   // 32768
#define NZ_   (R_*R_)   // 65536
#define EPS_  1e-5f
#define INF_  1e9f

// ---------------- scratch (static device globals; no allocation) ----------------
__device__ __nv_bfloat16 g_mh [NROW_*CM_];   // LN(m) hi
__device__ __nv_bfloat16 g_ml [NROW_*CM_];   // LN(m) lo
__device__ __nv_bfloat16 g_wth[1024*CM_];    // [n][k] transposed qkvg weights hi
__device__ __nv_bfloat16 g_wtl[1024*CM_];    // lo
__device__ __nv_bfloat16 g_woth[HC_*CM_];    // wo transposed hi  [n][k]
__device__ __nv_bfloat16 g_wotl[HC_*CM_];    // lo
__device__ __nv_bfloat16 g_ogh[NROW_*HC_];   // o*g hi
__device__ __nv_bfloat16 g_ogl[NROW_*HC_];   // o*g lo
__device__ float g_q  [NROW_*HC_];
__device__ float g_k  [NROW_*HC_];
__device__ float g_v  [NROW_*HC_];
__device__ float g_g  [NROW_*HC_];
__device__ float g_zb [H_*NZ_];              // pair bias [H][R][R]

// ---------------- helpers ----------------
__device__ __forceinline__ void bf16split(float x, __nv_bfloat16& h, __nv_bfloat16& l) {
    h = __float2bfloat16(x);
    l = __float2bfloat16(x - __bfloat162float(h));
}

__device__ __forceinline__ void mma16816(float* d, const uint32_t* a, const uint32_t* b) {
    asm volatile(
        "mma.sync.aligned.m16n8k16.row.col.f32.bf16.bf16.f32 "
        "{%0,%1,%2,%3}, {%4,%5,%6,%7}, {%8,%9}, {%0,%1,%2,%3};\n"
        : "+f"(d[0]), "+f"(d[1]), "+f"(d[2]), "+f"(d[3])
        : "r"(a[0]), "r"(a[1]), "r"(a[2]), "r"(a[3]), "r"(b[0]), "r"(b[1]));
}

// ---------------- kernel 1: LayerNorm over m rows -> bf16 hi/lo planes ----------------
__global__ void ln_m_kernel(const float* __restrict__ m,
                            const float* __restrict__ gam,
                            const float* __restrict__ bet) {
    const int row = blockIdx.x;
    const int t = threadIdx.x;   // 0..63
    const float4 x = ((const float4*)(m + (size_t)row * CM_))[t];
    float s = x.x + x.y + x.z + x.w;
    float q = x.x*x.x + x.y*x.y + x.z*x.z + x.w*x.w;
    #pragma unroll
    for (int o = 16; o > 0; o >>= 1) {
        s += __shfl_down_sync(0xffffffffu, s, o);
        q += __shfl_down_sync(0xffffffffu, q, o);
    }
    __shared__ float ss[2], sq[2];
    if ((t & 31) == 0) { ss[t >> 5] = s; sq[t >> 5] = q; }
    __syncthreads();
    const float mu  = (ss[0] + ss[1]) * (1.0f / CM_);
    const float var = (sq[0] + sq[1]) * (1.0f / CM_) - mu * mu;
    const float rs  = rsqrtf(var + EPS_);
    const float4 gv = ((const float4*)gam)[t];
    const float4 bv = ((const float4*)bet)[t];
    float y[4];
    y[0] = (x.x - mu) * rs * gv.x + bv.x;
    y[1] = (x.y - mu) * rs * gv.y + bv.y;
    y[2] = (x.z - mu) * rs * gv.z + bv.z;
    y[3] = (x.w - mu) * rs * gv.w + bv.w;
    __nv_bfloat16 hv[4], lv[4];
    #pragma unroll
    for (int j = 0; j < 4; j++) bf16split(y[j], hv[j], lv[j]);
    *(uint2*)&g_mh[(size_t)row * CM_ + t * 4] = *(uint2*)hv;
    *(uint2*)&g_ml[(size_t)row * CM_ + t * 4] = *(uint2*)lv;
}

// ---------------- kernel: weight transpose + split: w[k][n] -> Bt[n][k] hi/lo ----------------
// grid = K (256), block = 256 (n)
__global__ void wconv_kernel(const float* __restrict__ w,
                             __nv_bfloat16* __restrict__ bth,
                             __nv_bfloat16* __restrict__ btl,
                             int nOff) {
    const int k = blockIdx.x;
    const int n = threadIdx.x;
    const float x = w[(size_t)k * 256 + n];
    __nv_bfloat16 h, l;
    bf16split(x, h, l);
    bth[(size_t)(nOff + n) * CM_ + k] = h;
    btl[(size_t)(nOff + n) * CM_ + k] = l;
}

// ---------------- kernel 2: pair bias, one warp per z-row ----------------
__global__ void __launch_bounds__(256) zb_kernel(const float* __restrict__ z,
                          const float* __restrict__ gam,
                          const float* __restrict__ bet,
                          const float* __restrict__ w_z) {
    const int t = threadIdx.x;
    const int w = t >> 5, l = t & 31;
    const int row0 = blockIdx.x * 8;
    const int row = row0 + w;
    __shared__ float outp[8][8];

    const float* zr = z + (size_t)row * CZ_;
    float x0 = zr[l], x1 = zr[l + 32], x2 = zr[l + 64], x3 = zr[l + 96];
    float s = x0 + x1 + x2 + x3;
    float q = x0*x0 + x1*x1 + x2*x2 + x3*x3;
    #pragma unroll
    for (int o = 16; o > 0; o >>= 1) {
        s += __shfl_xor_sync(0xffffffffu, s, o);
        q += __shfl_xor_sync(0xffffffffu, q, o);
    }
    const float mu  = s * (1.0f / CZ_);
    const float var = q * (1.0f / CZ_) - mu * mu;
    const float rs  = rsqrtf(var + EPS_);
    float xn[4];
    xn[0] = (x0 - mu) * rs * __ldg(gam + l)      + __ldg(bet + l);
    xn[1] = (x1 - mu) * rs * __ldg(gam + l + 32) + __ldg(bet + l + 32);
    xn[2] = (x2 - mu) * rs * __ldg(gam + l + 64) + __ldg(bet + l + 64);
    xn[3] = (x3 - mu) * rs * __ldg(gam + l + 96) + __ldg(bet + l + 96);

    float p[H_];
    #pragma unroll
    for (int h = 0; h < H_; h++) p[h] = 0.0f;
    #pragma unroll
    for (int i = 0; i < 4; i++) {
        const int c = l + 32 * i;
        #pragma unroll
        for (int h = 0; h < H_; h++) p[h] += xn[i] * __ldg(w_z + c * H_ + h);
    }
    #pragma unroll
    for (int o = 16; o > 0; o >>= 1) {
        #pragma unroll
        for (int h = 0; h < H_; h++) p[h] += __shfl_xor_sync(0xffffffffu, p[h], o);
    }
    if (l == 0) {
        #pragma unroll
        for (int h = 0; h < H_; h++) outp[w][h] = p[h];
    }
    __syncthreads();
    if (t < 64) {
        const int h = t >> 3, j = t & 7;
        g_zb[(size_t)h * NZ_ + row0 + j] = outp[j][h];
    }
}

// ---------------- MMA GEMM: C[M, N] = A[M,256] @ B[256, N], bf16 split x3 ----------------
// A: row-major hi/lo planes. Bt: [n][k] hi/lo planes. BM=128 BN=64 BK=32, 256 thr.
// FUSED=1: N=1024, block col slab selects dest {q(scale),k,v,g(sigmoid+bias)}.
// FUSED=0: N=256, dst0 with +bias.
template <int FUSED>
__global__ void __launch_bounds__(256, 2) mma_gemm(
        const __nv_bfloat16* __restrict__ Ah, const __nv_bfloat16* __restrict__ Al,
        const __nv_bfloat16* __restrict__ Bth, const __nv_bfloat16* __restrict__ Btl,
        const float* __restrict__ bias,
        float* __restrict__ dq, float* __restrict__ dk,
        float* __restrict__ dv, float* __restrict__ dg) {
    __shared__ __nv_bfloat16 AsH[128][40], AsL[128][40];
    __shared__ __nv_bfloat16 BsH[64][40],  BsL[64][40];
    const int t = threadIdx.x;
    const int lane = t & 31, wid = t >> 5;
    const int wm = (wid & 3) * 32;
    const int wn = (wid >> 2) * 32;
    const int row0 = blockIdx.y * 128;
    const int n0 = blockIdx.x * 64;

    float acc[2][4][4];
    #pragma unroll
    for (int a = 0; a < 2; a++)
        #pragma unroll
        for (int b = 0; b < 4; b++)
            #pragma unroll
            for (int c = 0; c < 4; c++) acc[a][b][c] = 0.0f;

    const int arow = t >> 1, aseg0 = (t & 1) * 2;
    const int bn = t >> 2, bseg = t & 3;
    const int fr = lane >> 2, fk = (lane & 3) * 2;

    for (int kt = 0; kt < 8; kt++) {
        const int k0 = kt * 32;
        #pragma unroll
        for (int i = 0; i < 2; i++) {
            const int seg = aseg0 + i;
            *(uint4*)&AsH[arow][seg * 8] =
                *(const uint4*)(Ah + (size_t)(row0 + arow) * CM_ + k0 + seg * 8);
            *(uint4*)&AsL[arow][seg * 8] =
                *(const uint4*)(Al + (size_t)(row0 + arow) * CM_ + k0 + seg * 8);
        }
        *(uint4*)&BsH[bn][bseg * 8] =
            *(const uint4*)(Bth + (size_t)(n0 + bn) * CM_ + k0 + bseg * 8);
        *(uint4*)&BsL[bn][bseg * 8] =
            *(const uint4*)(Btl + (size_t)(n0 + bn) * CM_ + k0 + bseg * 8);
        __syncthreads();
        #pragma unroll
        for (int ks = 0; ks < 2; ks++) {
            const int kk = ks * 16;
            uint32_t aH[2][4], aL[2][4], bH[4][2], bL[4][2];
            #pragma unroll
            for (int my = 0; my < 2; my++) {
                const int mr = wm + my * 16 + fr;
                aH[my][0] = *(const uint32_t*)&AsH[mr    ][kk + fk];
                aH[my][1] = *(const uint32_t*)&AsH[mr + 8][kk + fk];
                aH[my][2] = *(const uint32_t*)&AsH[mr    ][kk + fk + 8];
                aH[my][3] = *(const uint32_t*)&AsH[mr + 8][kk + fk + 8];
                aL[my][0] = *(const uint32_t*)&AsL[mr    ][kk + fk];
                aL[my][1] = *(const uint32_t*)&AsL[mr + 8][kk + fk];
                aL[my][2] = *(const uint32_t*)&AsL[mr    ][kk + fk + 8];
                aL[my][3] = *(const uint32_t*)&AsL[mr + 8][kk + fk + 8];
            }
            #pragma unroll
            for (int nx = 0; nx < 4; nx++) {
                const int nr = wn + nx * 8 + fr;
                bH[nx][0] = *(const uint32_t*)&BsH[nr][kk + fk];
                bH[nx][1] = *(const uint32_t*)&BsH[nr][kk + fk + 8];
                bL[nx][0] = *(const uint32_t*)&BsL[nr][kk + fk];
                bL[nx][1] = *(const uint32_t*)&BsL[nr][kk + fk + 8];
            }
            #pragma unroll
            for (int my = 0; my < 2; my++)
                #pragma unroll
                for (int nx = 0; nx < 4; nx++) {
                    mma16816(acc[my][nx], aH[my], bH[nx]);
                    mma16816(acc[my][nx], aH[my], bL[nx]);
                    mma16816(acc[my][nx], aL[my], bH[nx]);
                }
        }
        __syncthreads();
    }

    // epilogue
    float* dst; int op; int cbase;
    if (FUSED) {
        const int which = n0 >> 8;
        dst = (which == 0) ? dq : (which == 1) ? dk : (which == 2) ? dv : dg;
        op  = (which == 0) ? 0 : (which == 3) ? 2 : 1;
        cbase = n0 & 255;
    } else {
        dst = dq; op = 3; cbase = n0;
    }
    #pragma unroll
    for (int my = 0; my < 2; my++)
        #pragma unroll
        for (int nx = 0; nx < 4; nx++) {
            const int r = row0 + wm + my * 16 + fr;
            const int c = cbase + wn + nx * 8 + fk;
            #pragma unroll
            for (int half = 0; half < 2; half++) {
                float v0 = acc[my][nx][half * 2 + 0];
                float v1 = acc[my][nx][half * 2 + 1];
                const int rr = r + half * 8;
                if (op == 0) {
                    const float sc = 0.17677669529663688f;  // 1/sqrt(32)
                    v0 *= sc; v1 *= sc;
                } else if (op == 2) {
                    v0 = 1.0f / (1.0f + __expf(-(v0 + bias[c])));
                    v1 = 1.0f / (1.0f + __expf(-(v1 + bias[c + 1])));
                } else if (op == 3) {
                    v0 += bias[c]; v1 += bias[c + 1];
                }
                float2 o2; o2.x = v0; o2.y = v1;
                *(float2*)(dst + (size_t)rr * HC_ + c) = o2;
            }
        }
}

// ---------------- kernel 4: fused attention, chunked online softmax ----------------
// grid = (H, S); block = 256 (one thread per query row). writes o*g as bf16 hi/lo.
__global__ void __launch_bounds__(256, 2) attn_kernel(const float* __restrict__ mask) {
    const int h = blockIdx.x;
    const int s = blockIdx.y;
    const int t = threadIdx.x;
    __shared__ float ks[16][32];
    __shared__ float vs[16][32];
    __shared__ float mb[256];

    float qv[32];
    {
        const float* qp = g_q + ((size_t)(s * R_ + t)) * HC_ + h * CH_;
        #pragma unroll
        for (int i = 0; i < 8; i++) {
            const float4 f = *(const float4*)(qp + i * 4);
            qv[i*4+0] = f.x; qv[i*4+1] = f.y; qv[i*4+2] = f.z; qv[i*4+3] = f.w;
        }
    }
    mb[t] = INF_ * (mask[(size_t)s * R_ + t] - 1.0f);

    float acc[32];
    #pragma unroll
    for (int c = 0; c < 32; c++) acc[c] = 0.0f;
    float mrun = -3.0e38f, lrun = 0.0f;

    const float* zbrow = g_zb + (size_t)h * NZ_ + (size_t)t * R_;

    for (int jc = 0; jc < 16; jc++) {
        const int j0 = jc * 16;
        __syncthreads();
        if (t < 128) {
            const int rr = t >> 3, c4 = t & 7;
            const float4 f = *(const float4*)(g_k + ((size_t)(s * R_ + j0 + rr)) * HC_ + h * CH_ + c4 * 4);
            *(float4*)&ks[rr][c4 * 4] = f;
        } else {
            const int t2 = t - 128;
            const int rr = t2 >> 3, c4 = t2 & 7;
            const float4 f = *(const float4*)(g_v + ((size_t)(s * R_ + j0 + rr)) * HC_ + h * CH_ + c4 * 4);
            *(float4*)&vs[rr][c4 * 4] = f;
        }
        __syncthreads();

        float l[16];
        #pragma unroll
        for (int iq = 0; iq < 4; iq++) {
            const float4 f = *(const float4*)(zbrow + j0 + iq * 4);
            l[iq*4+0] = f.x; l[iq*4+1] = f.y; l[iq*4+2] = f.z; l[iq*4+3] = f.w;
        }
        #pragma unroll
        for (int jj = 0; jj < 16; jj++) {
            float d0 = 0.f, d1 = 0.f, d2 = 0.f, d3 = 0.f;
            const float4 k0 = *(const float4*)&ks[jj][0];
            const float4 k1 = *(const float4*)&ks[jj][4];
            const float4 k2 = *(const float4*)&ks[jj][8];
            const float4 k3 = *(const float4*)&ks[jj][12];
            const float4 k4 = *(const float4*)&ks[jj][16];
            const float4 k5 = *(const float4*)&ks[jj][20];
            const float4 k6 = *(const float4*)&ks[jj][24];
            const float4 k7 = *(const float4*)&ks[jj][28];
            d0 += qv[0]*k0.x + qv[1]*k0.y + qv[2]*k0.z + qv[3]*k0.w;
            d1 += qv[4]*k1.x + qv[5]*k1.y + qv[6]*k1.z + qv[7]*k1.w;
            d2 += qv[8]*k2.x + qv[9]*k2.y + qv[10]*k2.z + qv[11]*k2.w;
            d3 += qv[12]*k3.x + qv[13]*k3.y + qv[14]*k3.z + qv[15]*k3.w;
            d0 += qv[16]*k4.x + qv[17]*k4.y + qv[18]*k4.z + qv[19]*k4.w;
            d1 += qv[20]*k5.x + qv[21]*k5.y + qv[22]*k5.z + qv[23]*k5.w;
            d2 += qv[24]*k6.x + qv[25]*k6.y + qv[26]*k6.z + qv[27]*k6.w;
            d3 += qv[28]*k7.x + qv[29]*k7.y + qv[30]*k7.z + qv[31]*k7.w;
            l[jj] += (d0 + d1) + (d2 + d3) + mb[j0 + jj];
        }
        float cmax = l[0];
        #pragma unroll
        for (int jj = 1; jj < 16; jj++) cmax = fmaxf(cmax, l[jj]);
        if (cmax > mrun) {
            const float sc = __expf(mrun - cmax);
            lrun *= sc;
            #pragma unroll
            for (int c = 0; c < 32; c++) acc[c] *= sc;
            mrun = cmax;
        }
        #pragma unroll
        for (int jj = 0; jj < 16; jj++) {
            const float p = __expf(l[jj] - mrun);
            lrun += p;
            #pragma unroll
            for (int i = 0; i < 8; i++) {
                const float4 vv = *(const float4*)&vs[jj][i * 4];
                acc[i*4+0] += p * vv.x;
                acc[i*4+1] += p * vv.y;
                acc[i*4+2] += p * vv.z;
                acc[i*4+3] += p * vv.w;
            }
        }
    }
    const float inv = 1.0f / lrun;
    const float* gp = g_g + ((size_t)(s * R_ + t)) * HC_ + h * CH_;
    const size_t obase = ((size_t)(s * R_ + t)) * HC_ + h * CH_;
    #pragma unroll
    for (int i = 0; i < 8; i++) {
        const float4 gf = *(const float4*)(gp + i * 4);
        float o[4];
        o[0] = acc[i*4+0] * inv * gf.x;
        o[1] = acc[i*4+1] * inv * gf.y;
        o[2] = acc[i*4+2] * inv * gf.z;
        o[3] = acc[i*4+3] * inv * gf.w;
        __nv_bfloat16 hv[4], lv[4];
        #pragma unroll
        for (int j = 0; j < 4; j++) bf16split(o[j], hv[j], lv[j]);
        *(uint2*)&g_ogh[obase + i * 4] = *(uint2*)hv;
        *(uint2*)&g_ogl[obase + i * 4] = *(uint2*)lv;
    }
}

// ---------------- launch ----------------
extern "C" void kernel_launch(void* const* d_in, const int* in_sizes, int n_in,
                              void* d_out, int out_size) {
    const float* m      = (const float*)d_in[0];
    const float* z      = (const float*)d_in[1];
    const float* mask   = (const float*)d_in[2];
    const float* ln_m_g = (const float*)d_in[3];
    const float* ln_m_b = (const float*)d_in[4];
    const float* ln_z_g = (const float*)d_in[5];
    const float* ln_z_b = (const float*)d_in[6];
    const float* w_z    = (const float*)d_in[7];
    const float* wq     = (const float*)d_in[8];
    const float* wk     = (const float*)d_in[9];
    const float* wv     = (const float*)d_in[10];
    const float* wg     = (const float*)d_in[11];
    const float* bg     = (const float*)d_in[12];
    const float* wo     = (const float*)d_in[13];
    const float* bo     = (const float*)d_in[14];
    float* out = (float*)d_out;

    __nv_bfloat16 *p_mh, *p_ml, *p_wth, *p_wtl, *p_woth, *p_wotl, *p_ogh, *p_ogl;
    float *p_q, *p_k, *p_v, *p_g;
    cudaGetSymbolAddress((void**)&p_mh,   g_mh);
    cudaGetSymbolAddress((void**)&p_ml,   g_ml);
    cudaGetSymbolAddress((void**)&p_wth,  g_wth);
    cudaGetSymbolAddress((void**)&p_wtl,  g_wtl);
    cudaGetSymbolAddress((void**)&p_woth, g_woth);
    cudaGetSymbolAddress((void**)&p_wotl, g_wotl);
    cudaGetSymbolAddress((void**)&p_ogh,  g_ogh);
    cudaGetSymbolAddress((void**)&p_ogl,  g_ogl);
    cudaGetSymbolAddress((void**)&p_q,    g_q);
    cudaGetSymbolAddress((void**)&p_k,    g_k);
    cudaGetSymbolAddress((void**)&p_v,    g_v);
    cudaGetSymbolAddress((void**)&p_g,    g_g);

    ln_m_kernel<<<NROW_, 64>>>(m, ln_m_g, ln_m_b);
    wconv_kernel<<<CM_, 256>>>(wq, p_wth, p_wtl, 0);
    wconv_kernel<<<CM_, 256>>>(wk, p_wth, p_wtl, 256);
    wconv_kernel<<<CM_, 256>>>(wv, p_wth, p_wtl, 512);
    wconv_kernel<<<CM_, 256>>>(wg, p_wth, p_wtl, 768);
    wconv_kernel<<<HC_, 256>>>(wo, p_woth, p_wotl, 0);
    zb_kernel<<<NZ_ / 8, 256>>>(z, ln_z_g, ln_z_b, w_z);

    mma_gemm<1><<<dim3(16, NROW_ / 128), 256>>>(p_mh, p_ml, p_wth, p_wtl, bg,
                                                p_q, p_k, p_v, p_g);

    attn_kernel<<<dim3(H_, S_), 256>>>(mask);

    mma_gemm<0><<<dim3(4, NROW_ / 128), 256>>>(p_ogh, p_ogl, p_woth, p_wotl, bo,
                                               out, nullptr, nullptr, nullptr);
}

// round 5
// speedup vs baseline: 1.7191x; 1.1902x over previous
#include <cuda_runtime.h>
#include <cuda_bf16.h>
#include <cstdint>

// ---------------- problem constants ----------------
#define S_   128
#define R_   256
#define CM_  256
#define CZ_  128
#define H_   8
#define CH_  32
#define HC_  256
#define NROW_ (S_*R_)   // 32768
#define NZ_   (R_*R_)   // 65536
#define EPS_  1e-5f
#define INF_  1e9f

// ---------------- scratch (static device globals; no allocation) ----------------
__device__ __align__(16) __nv_bfloat16 g_mh [NROW_*CM_];   // LN(m) hi
__device__ __align__(16) __nv_bfloat16 g_ml [NROW_*CM_];   // LN(m) lo
__device__ __align__(16) __nv_bfloat16 g_wth[1024*CM_];    // [n][k] qkvg weights hi
__device__ __align__(16) __nv_bfloat16 g_wtl[1024*CM_];    // lo
__device__ __align__(16) __nv_bfloat16 g_woth[HC_*CM_];    // wo [n][k] hi
__device__ __align__(16) __nv_bfloat16 g_wotl[HC_*CM_];    // lo
__device__ __align__(16) __nv_bfloat16 g_qh [NROW_*HC_];   // q hi (scaled)
__device__ __align__(16) __nv_bfloat16 g_ql [NROW_*HC_];
__device__ __align__(16) __nv_bfloat16 g_kh [NROW_*HC_];
__device__ __align__(16) __nv_bfloat16 g_kl [NROW_*HC_];
__device__ __align__(16) __nv_bfloat16 g_vth[NROW_*HC_];   // V^T [s][h][d][key] hi
__device__ __align__(16) __nv_bfloat16 g_vtl[NROW_*HC_];
__device__ __align__(16) __nv_bfloat16 g_ogh[NROW_*HC_];   // o*g hi
__device__ __align__(16) __nv_bfloat16 g_ogl[NROW_*HC_];
__device__ float g_g  [NROW_*HC_];               // sigmoid gate (fp32)
__device__ float g_zb [H_*NZ_];                  // pair bias [H][R][R]

// ---------------- helpers ----------------
__device__ __forceinline__ void bf16split(float x, __nv_bfloat16& h, __nv_bfloat16& l) {
    h = __float2bfloat16(x);
    l = __float2bfloat16(x - __bfloat162float(h));
}
// pack {lo = a, hi = b} as bf16x2
__device__ __forceinline__ uint32_t packbf(float a, float b) {
    uint32_t r;
    asm("cvt.rn.bf16x2.f32 %0, %1, %2;" : "=r"(r) : "f"(b), "f"(a));
    return r;
}
__device__ __forceinline__ void mma16816(float* d, const uint32_t* a, const uint32_t* b) {
    asm volatile(
        "mma.sync.aligned.m16n8k16.row.col.f32.bf16.bf16.f32 "
        "{%0,%1,%2,%3}, {%4,%5,%6,%7}, {%8,%9}, {%0,%1,%2,%3};\n"
        : "+f"(d[0]), "+f"(d[1]), "+f"(d[2]), "+f"(d[3])
        : "r"(a[0]), "r"(a[1]), "r"(a[2]), "r"(a[3]), "r"(b[0]), "r"(b[1]));
}

// ---------------- kernel 1: LayerNorm over m rows -> bf16 hi/lo planes ----------------
__global__ void ln_m_kernel(const float* __restrict__ m,
                            const float* __restrict__ gam,
                            const float* __restrict__ bet) {
    const int row = blockIdx.x;
    const int t = threadIdx.x;   // 0..63
    const float4 x = ((const float4*)(m + (size_t)row * CM_))[t];
    float s = x.x + x.y + x.z + x.w;
    float q = x.x*x.x + x.y*x.y + x.z*x.z + x.w*x.w;
    #pragma unroll
    for (int o = 16; o > 0; o >>= 1) {
        s += __shfl_down_sync(0xffffffffu, s, o);
        q += __shfl_down_sync(0xffffffffu, q, o);
    }
    __shared__ float ss[2], sq[2];
    if ((t & 31) == 0) { ss[t >> 5] = s; sq[t >> 5] = q; }
    __syncthreads();
    const float mu  = (ss[0] + ss[1]) * (1.0f / CM_);
    const float var = (sq[0] + sq[1]) * (1.0f / CM_) - mu * mu;
    const float rs  = rsqrtf(var + EPS_);
    const float4 gv = ((const float4*)gam)[t];
    const float4 bv = ((const float4*)bet)[t];
    float y[4];
    y[0] = (x.x - mu) * rs * gv.x + bv.x;
    y[1] = (x.y - mu) * rs * gv.y + bv.y;
    y[2] = (x.z - mu) * rs * gv.z + bv.z;
    y[3] = (x.w - mu) * rs * gv.w + bv.w;
    __nv_bfloat16 hv[4], lv[4];
    #pragma unroll
    for (int j = 0; j < 4; j++) bf16split(y[j], hv[j], lv[j]);
    *(uint2*)&g_mh[(size_t)row * CM_ + t * 4] = *(uint2*)hv;
    *(uint2*)&g_ml[(size_t)row * CM_ + t * 4] = *(uint2*)lv;
}

// ---------------- merged weight transpose + split ----------------
// grid (256, 5): y selects {wq,wk,wv,wg,wo}
__global__ void wconv_all(const float* __restrict__ wq, const float* __restrict__ wk,
                          const float* __restrict__ wv, const float* __restrict__ wg,
                          const float* __restrict__ wo) {
    const int k = blockIdx.x, which = blockIdx.y;
    const int n = threadIdx.x;
    const float* w = (which == 0) ? wq : (which == 1) ? wk :
                     (which == 2) ? wv : (which == 3) ? wg : wo;
    const float x = w[(size_t)k * 256 + n];
    __nv_bfloat16 h, l;
    bf16split(x, h, l);
    if (which < 4) {
        g_wth[(size_t)(which * 256 + n) * CM_ + k] = h;
        g_wtl[(size_t)(which * 256 + n) * CM_ + k] = l;
    } else {
        g_woth[(size_t)n * CM_ + k] = h;
        g_wotl[(size_t)n * CM_ + k] = l;
    }
}

// ---------------- kernel 2: pair bias, one warp per z-row ----------------
__global__ void __launch_bounds__(256) zb_kernel(const float* __restrict__ z,
                          const float* __restrict__ gam,
                          const float* __restrict__ bet,
                          const float* __restrict__ w_z) {
    const int t = threadIdx.x;
    const int w = t >> 5, l = t & 31;
    const int row0 = blockIdx.x * 8;
    const int row = row0 + w;
    __shared__ float outp[8][8];

    const float* zr = z + (size_t)row * CZ_;
    float x0 = zr[l], x1 = zr[l + 32], x2 = zr[l + 64], x3 = zr[l + 96];
    float s = x0 + x1 + x2 + x3;
    float q = x0*x0 + x1*x1 + x2*x2 + x3*x3;
    #pragma unroll
    for (int o = 16; o > 0; o >>= 1) {
        s += __shfl_xor_sync(0xffffffffu, s, o);
        q += __shfl_xor_sync(0xffffffffu, q, o);
    }
    const float mu  = s * (1.0f / CZ_);
    const float var = q * (1.0f / CZ_) - mu * mu;
    const float rs  = rsqrtf(var + EPS_);
    float xn[4];
    xn[0] = (x0 - mu) * rs * __ldg(gam + l)      + __ldg(bet + l);
    xn[1] = (x1 - mu) * rs * __ldg(gam + l + 32) + __ldg(bet + l + 32);
    xn[2] = (x2 - mu) * rs * __ldg(gam + l + 64) + __ldg(bet + l + 64);
    xn[3] = (x3 - mu) * rs * __ldg(gam + l + 96) + __ldg(bet + l + 96);

    float p[H_];
    #pragma unroll
    for (int h = 0; h < H_; h++) p[h] = 0.0f;
    #pragma unroll
    for (int i = 0; i < 4; i++) {
        const int c = l + 32 * i;
        #pragma unroll
        for (int h = 0; h < H_; h++) p[h] += xn[i] * __ldg(w_z + c * H_ + h);
    }
    #pragma unroll
    for (int o = 16; o > 0; o >>= 1) {
        #pragma unroll
        for (int h = 0; h < H_; h++) p[h] += __shfl_xor_sync(0xffffffffu, p[h], o);
    }
    if (l == 0) {
        #pragma unroll
        for (int h = 0; h < H_; h++) outp[w][h] = p[h];
    }
    __syncthreads();
    if (t < 64) {
        const int h = t >> 3, j = t & 7;
        g_zb[(size_t)h * NZ_ + row0 + j] = outp[j][h];
    }
}

// ---------------- MMA GEMM: C[M, N] = A[M,256] @ B[256, N], bf16 split x3 ----------------
// FUSED=1: N=1024, per-slab epilogue -> q/k bf16 planes, v transposed planes, g fp32.
// FUSED=0: N=256, float out + bias.
template <int FUSED>
__global__ void __launch_bounds__(256, 2) mma_gemm(
        const __nv_bfloat16* __restrict__ Ah, const __nv_bfloat16* __restrict__ Al,
        const __nv_bfloat16* __restrict__ Bth, const __nv_bfloat16* __restrict__ Btl,
        const float* __restrict__ bias, float* __restrict__ outF) {
    __shared__ __nv_bfloat16 AsH[128][40], AsL[128][40];
    __shared__ __nv_bfloat16 BsH[64][40],  BsL[64][40];
    const int t = threadIdx.x;
    const int lane = t & 31, wid = t >> 5;
    const int wm = (wid & 3) * 32;
    const int wn = (wid >> 2) * 32;
    const int row0 = blockIdx.y * 128;
    const int n0 = blockIdx.x * 64;

    float acc[2][4][4];
    #pragma unroll
    for (int a = 0; a < 2; a++)
        #pragma unroll
        for (int b = 0; b < 4; b++)
            #pragma unroll
            for (int c = 0; c < 4; c++) acc[a][b][c] = 0.0f;

    const int arow = t >> 1, aseg0 = (t & 1) * 2;
    const int bn = t >> 2, bseg = t & 3;
    const int fr = lane >> 2, fk = (lane & 3) * 2;

    for (int kt = 0; kt < 8; kt++) {
        const int k0 = kt * 32;
        #pragma unroll
        for (int i = 0; i < 2; i++) {
            const int seg = aseg0 + i;
            *(uint4*)&AsH[arow][seg * 8] =
                *(const uint4*)(Ah + (size_t)(row0 + arow) * CM_ + k0 + seg * 8);
            *(uint4*)&AsL[arow][seg * 8] =
                *(const uint4*)(Al + (size_t)(row0 + arow) * CM_ + k0 + seg * 8);
        }
        *(uint4*)&BsH[bn][bseg * 8] =
            *(const uint4*)(Bth + (size_t)(n0 + bn) * CM_ + k0 + bseg * 8);
        *(uint4*)&BsL[bn][bseg * 8] =
            *(const uint4*)(Btl + (size_t)(n0 + bn) * CM_ + k0 + bseg * 8);
        __syncthreads();
        #pragma unroll
        for (int ks = 0; ks < 2; ks++) {
            const int kk = ks * 16;
            uint32_t aH[2][4], aL[2][4], bH[4][2], bL[4][2];
            #pragma unroll
            for (int my = 0; my < 2; my++) {
                const int mr = wm + my * 16 + fr;
                aH[my][0] = *(const uint32_t*)&AsH[mr    ][kk + fk];
                aH[my][1] = *(const uint32_t*)&AsH[mr + 8][kk + fk];
                aH[my][2] = *(const uint32_t*)&AsH[mr    ][kk + fk + 8];
                aH[my][3] = *(const uint32_t*)&AsH[mr + 8][kk + fk + 8];
                aL[my][0] = *(const uint32_t*)&AsL[mr    ][kk + fk];
                aL[my][1] = *(const uint32_t*)&AsL[mr + 8][kk + fk];
                aL[my][2] = *(const uint32_t*)&AsL[mr    ][kk + fk + 8];
                aL[my][3] = *(const uint32_t*)&AsL[mr + 8][kk + fk + 8];
            }
            #pragma unroll
            for (int nx = 0; nx < 4; nx++) {
                const int nr = wn + nx * 8 + fr;
                bH[nx][0] = *(const uint32_t*)&BsH[nr][kk + fk];
                bH[nx][1] = *(const uint32_t*)&BsH[nr][kk + fk + 8];
                bL[nx][0] = *(const uint32_t*)&BsL[nr][kk + fk];
                bL[nx][1] = *(const uint32_t*)&BsL[nr][kk + fk + 8];
            }
            #pragma unroll
            for (int my = 0; my < 2; my++)
                #pragma unroll
                for (int nx = 0; nx < 4; nx++) {
                    mma16816(acc[my][nx], aH[my], bH[nx]);
                    mma16816(acc[my][nx], aH[my], bL[nx]);
                    mma16816(acc[my][nx], aL[my], bH[nx]);
                }
        }
        __syncthreads();
    }

    const int which = FUSED ? (n0 >> 8) : 3;
    const int cbase = FUSED ? (n0 & 255) : n0;
    #pragma unroll
    for (int my = 0; my < 2; my++)
        #pragma unroll
        for (int nx = 0; nx < 4; nx++) {
            #pragma unroll
            for (int half = 0; half < 2; half++) {
                float v0 = acc[my][nx][half * 2 + 0];
                float v1 = acc[my][nx][half * 2 + 1];
                const int rr = row0 + wm + my * 16 + fr + half * 8;
                const int c = cbase + wn + nx * 8 + fk;
                if (!FUSED) {
                    float2 o2; o2.x = v0 + bias[c]; o2.y = v1 + bias[c + 1];
                    *(float2*)(outF + (size_t)rr * HC_ + c) = o2;
                } else if (which == 0) {        // q: scale, split
                    const float sc = 0.17677669529663688f;
                    v0 *= sc; v1 *= sc;
                    __nv_bfloat16 h0, l0, h1, l1;
                    bf16split(v0, h0, l0); bf16split(v1, h1, l1);
                    *(uint32_t*)&g_qh[(size_t)rr * HC_ + c] = ((uint32_t)*(uint16_t*)&h1 << 16) | *(uint16_t*)&h0;
                    *(uint32_t*)&g_ql[(size_t)rr * HC_ + c] = ((uint32_t)*(uint16_t*)&l1 << 16) | *(uint16_t*)&l0;
                } else if (which == 1) {        // k: split
                    __nv_bfloat16 h0, l0, h1, l1;
                    bf16split(v0, h0, l0); bf16split(v1, h1, l1);
                    *(uint32_t*)&g_kh[(size_t)rr * HC_ + c] = ((uint32_t)*(uint16_t*)&h1 << 16) | *(uint16_t*)&h0;
                    *(uint32_t*)&g_kl[(size_t)rr * HC_ + c] = ((uint32_t)*(uint16_t*)&l1 << 16) | *(uint16_t*)&l0;
                } else if (which == 2) {        // v: transposed split  [s][h][d][key]
                    const int key = rr & 255, sidx = rr >> 8;
                    const int hh = c >> 5, d = c & 31;
                    __nv_bfloat16 h0, l0, h1, l1;
                    bf16split(v0, h0, l0); bf16split(v1, h1, l1);
                    const size_t b0i = ((size_t)(sidx * H_ + hh) * CH_ + d) * R_ + key;
                    g_vth[b0i] = h0;       g_vtl[b0i] = l0;
                    g_vth[b0i + R_] = h1;  g_vtl[b0i + R_] = l1;   // d+1
                } else {                        // g: sigmoid -> fp32
                    float2 o2;
                    o2.x = 1.0f / (1.0f + __expf(-(v0 + bias[c])));
                    o2.y = 1.0f / (1.0f + __expf(-(v1 + bias[c + 1])));
                    *(float2*)(g_g + (size_t)rr * HC_ + c) = o2;
                }
            }
        }
}

// ---------------- kernel 4: flash-attention with HMMA, bf16 split x3 ----------------
// grid (H, S), 256 threads (8 warps x 32 query rows). Writes o*g bf16 hi/lo.
__global__ void __launch_bounds__(256, 1) attn_mma_kernel(const float* __restrict__ mask) {
    const int h = blockIdx.x, s = blockIdx.y;
    const int t = threadIdx.x;
    const int w = t >> 5, lane = t & 31;
    const int fr = lane >> 2, q2 = (lane & 3) * 2;
    __shared__ float mb[256];
    mb[t] = INF_ * (mask[(size_t)s * R_ + t] - 1.0f);
    __syncthreads();

    // ---- Q fragments (A operand), rows w*32 + my*16 + {fr, fr+8} ----
    uint32_t AqH[2][2][4], AqL[2][2][4];
    {
        const size_t qbase = ((size_t)(s * R_ + w * 32)) * HC_ + h * CH_;
        #pragma unroll
        for (int my = 0; my < 2; my++)
            #pragma unroll
            for (int half = 0; half < 2; half++) {
                const size_t rb = qbase + (size_t)(my * 16 + half * 8 + fr) * HC_;
                #pragma unroll
                for (int ks = 0; ks < 2; ks++) {
                    AqH[my][ks][half]     = *(const uint32_t*)(g_qh + rb + ks * 16 + q2);
                    AqH[my][ks][half + 2] = *(const uint32_t*)(g_qh + rb + ks * 16 + q2 + 8);
                    AqL[my][ks][half]     = *(const uint32_t*)(g_ql + rb + ks * 16 + q2);
                    AqL[my][ks][half + 2] = *(const uint32_t*)(g_ql + rb + ks * 16 + q2 + 8);
                }
            }
    }

    float oa[2][4][4];
    #pragma unroll
    for (int a = 0; a < 2; a++)
        #pragma unroll
        for (int b = 0; b < 4; b++)
            #pragma unroll
            for (int c = 0; c < 4; c++) oa[a][b][c] = 0.0f;
    float mrun[2][2], lrun[2][2];
    #pragma unroll
    for (int a = 0; a < 2; a++) { mrun[a][0] = mrun[a][1] = -1.0e30f; lrun[a][0] = lrun[a][1] = 0.0f; }

    const float* zb_h = g_zb + (size_t)h * NZ_;
    const __nv_bfloat16* kh_s = g_kh + ((size_t)s * R_) * HC_ + h * CH_;
    const __nv_bfloat16* kl_s = g_kl + ((size_t)s * R_) * HC_ + h * CH_;
    const __nv_bfloat16* vth_s = g_vth + (size_t)(s * H_ + h) * CH_ * R_;
    const __nv_bfloat16* vtl_s = g_vtl + (size_t)(s * H_ + h) * CH_ * R_;

    for (int jc = 0; jc < 8; jc++) {
        const int j0 = jc * 32;
        // ---- logits init with pair bias + mask bias ----
        float la[2][4][4];
        #pragma unroll
        for (int my = 0; my < 2; my++)
            #pragma unroll
            for (int nt = 0; nt < 4; nt++)
                #pragma unroll
                for (int half = 0; half < 2; half++) {
                    const int qrow = w * 32 + my * 16 + half * 8 + fr;
                    const float2 zv = *(const float2*)(zb_h + (size_t)qrow * R_ + j0 + nt * 8 + q2);
                    la[my][nt][half * 2 + 0] = zv.x + mb[j0 + nt * 8 + q2];
                    la[my][nt][half * 2 + 1] = zv.y + mb[j0 + nt * 8 + q2 + 1];
                }
        // ---- QK^T: 3-term split ----
        #pragma unroll
        for (int ks = 0; ks < 2; ks++) {
            uint32_t bh[4][2], bl[4][2];
            #pragma unroll
            for (int nt = 0; nt < 4; nt++) {
                const size_t kb = (size_t)(j0 + nt * 8 + fr) * HC_ + ks * 16 + q2;
                bh[nt][0] = *(const uint32_t*)(kh_s + kb);
                bh[nt][1] = *(const uint32_t*)(kh_s + kb + 8);
                bl[nt][0] = *(const uint32_t*)(kl_s + kb);
                bl[nt][1] = *(const uint32_t*)(kl_s + kb + 8);
            }
            #pragma unroll
            for (int my = 0; my < 2; my++)
                #pragma unroll
                for (int nt = 0; nt < 4; nt++) {
                    mma16816(la[my][nt], AqH[my][ks], bh[nt]);
                    mma16816(la[my][nt], AqH[my][ks], bl[nt]);
                    mma16816(la[my][nt], AqL[my][ks], bh[nt]);
                }
        }
        // ---- online softmax (4 rows per thread: my x half) ----
        #pragma unroll
        for (int my = 0; my < 2; my++)
            #pragma unroll
            for (int half = 0; half < 2; half++) {
                float vmax = la[my][0][half * 2];
                #pragma unroll
                for (int nt = 0; nt < 4; nt++) {
                    vmax = fmaxf(vmax, la[my][nt][half * 2]);
                    vmax = fmaxf(vmax, la[my][nt][half * 2 + 1]);
                }
                vmax = fmaxf(vmax, __shfl_xor_sync(0xffffffffu, vmax, 1));
                vmax = fmaxf(vmax, __shfl_xor_sync(0xffffffffu, vmax, 2));
                const float mnew = fmaxf(mrun[my][half], vmax);
                const float fac = __expf(mrun[my][half] - mnew);
                mrun[my][half] = mnew;
                float rsum = 0.0f;
                #pragma unroll
                for (int nt = 0; nt < 4; nt++) {
                    float p0 = __expf(la[my][nt][half * 2] - mnew);
                    float p1 = __expf(la[my][nt][half * 2 + 1] - mnew);
                    la[my][nt][half * 2] = p0;
                    la[my][nt][half * 2 + 1] = p1;
                    rsum += p0 + p1;
                }
                rsum += __shfl_xor_sync(0xffffffffu, rsum, 1);
                rsum += __shfl_xor_sync(0xffffffffu, rsum, 2);
                lrun[my][half] = lrun[my][half] * fac + rsum;
                #pragma unroll
                for (int dt = 0; dt < 4; dt++) {
                    oa[my][dt][half * 2] *= fac;
                    oa[my][dt][half * 2 + 1] *= fac;
                }
            }
        // ---- P fragments (accumulator layout == A operand layout) ----
        uint32_t ApH[2][2][4], ApL[2][2][4];
        #pragma unroll
        for (int my = 0; my < 2; my++)
            #pragma unroll
            for (int kv = 0; kv < 2; kv++) {
                #pragma unroll
                for (int r = 0; r < 4; r++) {
                    const int nt = 2 * kv + (r >> 1);
                    const int hf = r & 1;
                    const float p0 = la[my][nt][hf * 2];
                    const float p1 = la[my][nt][hf * 2 + 1];
                    __nv_bfloat16 h0, l0, h1, l1;
                    bf16split(p0, h0, l0); bf16split(p1, h1, l1);
                    ApH[my][kv][r] = ((uint32_t)*(uint16_t*)&h1 << 16) | *(uint16_t*)&h0;
                    ApL[my][kv][r] = ((uint32_t)*(uint16_t*)&l1 << 16) | *(uint16_t*)&l0;
                }
            }
        // ---- PV: 3-term split; B from V^T gmem ----
        #pragma unroll
        for (int kv = 0; kv < 2; kv++) {
            uint32_t bvh[4][2], bvl[4][2];
            #pragma unroll
            for (int dt = 0; dt < 4; dt++) {
                const size_t vb = (size_t)(dt * 8 + fr) * R_ + j0 + kv * 16 + q2;
                bvh[dt][0] = *(const uint32_t*)(vth_s + vb);
                bvh[dt][1] = *(const uint32_t*)(vth_s + vb + 8);
                bvl[dt][0] = *(const uint32_t*)(vtl_s + vb);
                bvl[dt][1] = *(const uint32_t*)(vtl_s + vb + 8);
            }
            #pragma unroll
            for (int my = 0; my < 2; my++)
                #pragma unroll
                for (int dt = 0; dt < 4; dt++) {
                    mma16816(oa[my][dt], ApH[my][kv], bvh[dt]);
                    mma16816(oa[my][dt], ApH[my][kv], bvl[dt]);
                    mma16816(oa[my][dt], ApL[my][kv], bvh[dt]);
                }
        }
    }
    // ---- epilogue: normalize, gate, split, store ----
    #pragma unroll
    for (int my = 0; my < 2; my++)
        #pragma unroll
        for (int half = 0; half < 2; half++) {
            const float inv = 1.0f / lrun[my][half];
            const int grow = s * R_ + w * 32 + my * 16 + half * 8 + fr;
            #pragma unroll
            for (int dt = 0; dt < 4; dt++) {
                const int dim = dt * 8 + q2;
                const float2 gf = *(const float2*)(g_g + (size_t)grow * HC_ + h * CH_ + dim);
                const float o0 = oa[my][dt][half * 2] * inv * gf.x;
                const float o1 = oa[my][dt][half * 2 + 1] * inv * gf.y;
                __nv_bfloat16 h0, l0, h1, l1;
                bf16split(o0, h0, l0); bf16split(o1, h1, l1);
                *(uint32_t*)&g_ogh[(size_t)grow * HC_ + h * CH_ + dim] =
                    ((uint32_t)*(uint16_t*)&h1 << 16) | *(uint16_t*)&h0;
                *(uint32_t*)&g_ogl[(size_t)grow * HC_ + h * CH_ + dim] =
                    ((uint32_t)*(uint16_t*)&l1 << 16) | *(uint16_t*)&l0;
            }
        }
}

// ---------------- launch ----------------
extern "C" void kernel_launch(void* const* d_in, const int* in_sizes, int n_in,
                              void* d_out, int out_size) {
    const float* m      = (const float*)d_in[0];
    const float* z      = (const float*)d_in[1];
    const float* mask   = (const float*)d_in[2];
    const float* ln_m_g = (const float*)d_in[3];
    const float* ln_m_b = (const float*)d_in[4];
    const float* ln_z_g = (const float*)d_in[5];
    const float* ln_z_b = (const float*)d_in[6];
    const float* w_z    = (const float*)d_in[7];
    const float* wq     = (const float*)d_in[8];
    const float* wk     = (const float*)d_in[9];
    const float* wv     = (const float*)d_in[10];
    const float* wg     = (const float*)d_in[11];
    const float* bg     = (const float*)d_in[12];
    const float* wo     = (const float*)d_in[13];
    const float* bo     = (const float*)d_in[14];
    float* out = (float*)d_out;

    __nv_bfloat16 *p_mh, *p_ml, *p_wth, *p_wtl, *p_woth, *p_wotl, *p_ogh, *p_ogl;
    cudaGetSymbolAddress((void**)&p_mh,   g_mh);
    cudaGetSymbolAddress((void**)&p_ml,   g_ml);
    cudaGetSymbolAddress((void**)&p_wth,  g_wth);
    cudaGetSymbolAddress((void**)&p_wtl,  g_wtl);
    cudaGetSymbolAddress((void**)&p_woth, g_woth);
    cudaGetSymbolAddress((void**)&p_wotl, g_wotl);
    cudaGetSymbolAddress((void**)&p_ogh,  g_ogh);
    cudaGetSymbolAddress((void**)&p_ogl,  g_ogl);

    ln_m_kernel<<<NROW_, 64>>>(m, ln_m_g, ln_m_b);
    wconv_all<<<dim3(CM_, 5), 256>>>(wq, wk, wv, wg, wo);
    zb_kernel<<<NZ_ / 8, 256>>>(z, ln_z_g, ln_z_b, w_z);

    mma_gemm<1><<<dim3(16, NROW_ / 128), 256>>>(p_mh, p_ml, p_wth, p_wtl, bg, nullptr);

    attn_mma_kernel<<<dim3(H_, S_), 256>>>(mask);

    mma_gemm<0><<<dim3(4, NROW_ / 128), 256>>>(p_ogh, p_ogl, p_woth, p_wotl, bo, out);
}

// round 6
// speedup vs baseline: 1.8228x; 1.0603x over previous
#include <cuda_runtime.h>
#include <cuda_bf16.h>
#include <cstdint>

// ---------------- problem constants ----------------
#define S_   128
#define R_   256
#define CM_  256
#define CZ_  128
#define H_   8
#define CH_  32
#define HC_  256
#define NROW_ (S_*R_)   // 32768
#define NZ_   (R_*R_)   // 65536
#define EPS_  1e-5f
#define INF_  1e9f

// ---------------- scratch (static device globals; no allocation) ----------------
__device__ __align__(16) __nv_bfloat16 g_mh [NROW_*CM_];   // LN(m) hi
__device__ __align__(16) __nv_bfloat16 g_ml [NROW_*CM_];   // LN(m) lo
__device__ __align__(16) __nv_bfloat16 g_wth[1024*CM_];    // [n][k] qkvg weights hi
__device__ __align__(16) __nv_bfloat16 g_wtl[1024*CM_];    // lo
__device__ __align__(16) __nv_bfloat16 g_woth[HC_*CM_];    // wo [n][k] hi
__device__ __align__(16) __nv_bfloat16 g_wotl[HC_*CM_];    // lo
__device__ __align__(16) __nv_bfloat16 g_qh [NROW_*HC_];   // q hi (scaled)
__device__ __align__(16) __nv_bfloat16 g_ql [NROW_*HC_];
__device__ __align__(16) __nv_bfloat16 g_kh [NROW_*HC_];
__device__ __align__(16) __nv_bfloat16 g_kl [NROW_*HC_];
__device__ __align__(16) __nv_bfloat16 g_vth[NROW_*HC_];   // V^T [s][h][d][key] hi
__device__ __align__(16) __nv_bfloat16 g_vtl[NROW_*HC_];
__device__ __align__(16) __nv_bfloat16 g_ogh[NROW_*HC_];   // o*g hi
__device__ __align__(16) __nv_bfloat16 g_ogl[NROW_*HC_];
__device__ float g_g  [NROW_*HC_];               // sigmoid gate (fp32)
__device__ float g_zb [H_*NZ_];                  // pair bias [H][R][R]

// ---------------- helpers ----------------
__device__ __forceinline__ void bf16split(float x, __nv_bfloat16& h, __nv_bfloat16& l) {
    h = __float2bfloat16(x);
    l = __float2bfloat16(x - __bfloat162float(h));
}
__device__ __forceinline__ void mma16816(float* d, const uint32_t* a, const uint32_t* b) {
    asm volatile(
        "mma.sync.aligned.m16n8k16.row.col.f32.bf16.bf16.f32 "
        "{%0,%1,%2,%3}, {%4,%5,%6,%7}, {%8,%9}, {%0,%1,%2,%3};\n"
        : "+f"(d[0]), "+f"(d[1]), "+f"(d[2]), "+f"(d[3])
        : "r"(a[0]), "r"(a[1]), "r"(a[2]), "r"(a[3]), "r"(b[0]), "r"(b[1]));
}
__device__ __forceinline__ void ldsm_x4(uint32_t& r0, uint32_t& r1, uint32_t& r2, uint32_t& r3,
                                        const void* p) {
    uint32_t addr = (uint32_t)__cvta_generic_to_shared(p);
    asm volatile("ldmatrix.sync.aligned.m8n8.x4.shared.b16 {%0,%1,%2,%3}, [%4];"
        : "=r"(r0), "=r"(r1), "=r"(r2), "=r"(r3) : "r"(addr));
}

// ---------------- kernel 1: LayerNorm over m rows -> bf16 hi/lo planes ----------------
__global__ void ln_m_kernel(const float* __restrict__ m,
                            const float* __restrict__ gam,
                            const float* __restrict__ bet) {
    const int row = blockIdx.x;
    const int t = threadIdx.x;   // 0..63
    const float4 x = ((const float4*)(m + (size_t)row * CM_))[t];
    float s = x.x + x.y + x.z + x.w;
    float q = x.x*x.x + x.y*x.y + x.z*x.z + x.w*x.w;
    #pragma unroll
    for (int o = 16; o > 0; o >>= 1) {
        s += __shfl_down_sync(0xffffffffu, s, o);
        q += __shfl_down_sync(0xffffffffu, q, o);
    }
    __shared__ float ss[2], sq[2];
    if ((t & 31) == 0) { ss[t >> 5] = s; sq[t >> 5] = q; }
    __syncthreads();
    const float mu  = (ss[0] + ss[1]) * (1.0f / CM_);
    const float var = (sq[0] + sq[1]) * (1.0f / CM_) - mu * mu;
    const float rs  = rsqrtf(var + EPS_);
    const float4 gv = ((const float4*)gam)[t];
    const float4 bv = ((const float4*)bet)[t];
    float y[4];
    y[0] = (x.x - mu) * rs * gv.x + bv.x;
    y[1] = (x.y - mu) * rs * gv.y + bv.y;
    y[2] = (x.z - mu) * rs * gv.z + bv.z;
    y[3] = (x.w - mu) * rs * gv.w + bv.w;
    __nv_bfloat16 hv[4], lv[4];
    #pragma unroll
    for (int j = 0; j < 4; j++) bf16split(y[j], hv[j], lv[j]);
    *(uint2*)&g_mh[(size_t)row * CM_ + t * 4] = *(uint2*)hv;
    *(uint2*)&g_ml[(size_t)row * CM_ + t * 4] = *(uint2*)lv;
}

// ---------------- merged weight transpose + split ----------------
__global__ void wconv_all(const float* __restrict__ wq, const float* __restrict__ wk,
                          const float* __restrict__ wv, const float* __restrict__ wg,
                          const float* __restrict__ wo) {
    const int k = blockIdx.x, which = blockIdx.y;
    const int n = threadIdx.x;
    const float* w = (which == 0) ? wq : (which == 1) ? wk :
                     (which == 2) ? wv : (which == 3) ? wg : wo;
    const float x = w[(size_t)k * 256 + n];
    __nv_bfloat16 h, l;
    bf16split(x, h, l);
    if (which < 4) {
        g_wth[(size_t)(which * 256 + n) * CM_ + k] = h;
        g_wtl[(size_t)(which * 256 + n) * CM_ + k] = l;
    } else {
        g_woth[(size_t)n * CM_ + k] = h;
        g_wotl[(size_t)n * CM_ + k] = l;
    }
}

// ---------------- kernel 2: pair bias, one warp per z-row ----------------
__global__ void __launch_bounds__(256) zb_kernel(const float* __restrict__ z,
                          const float* __restrict__ gam,
                          const float* __restrict__ bet,
                          const float* __restrict__ w_z) {
    const int t = threadIdx.x;
    const int w = t >> 5, l = t & 31;
    const int row0 = blockIdx.x * 8;
    const int row = row0 + w;
    __shared__ float outp[8][8];

    const float* zr = z + (size_t)row * CZ_;
    float x0 = zr[l], x1 = zr[l + 32], x2 = zr[l + 64], x3 = zr[l + 96];
    float s = x0 + x1 + x2 + x3;
    float q = x0*x0 + x1*x1 + x2*x2 + x3*x3;
    #pragma unroll
    for (int o = 16; o > 0; o >>= 1) {
        s += __shfl_xor_sync(0xffffffffu, s, o);
        q += __shfl_xor_sync(0xffffffffu, q, o);
    }
    const float mu  = s * (1.0f / CZ_);
    const float var = q * (1.0f / CZ_) - mu * mu;
    const float rs  = rsqrtf(var + EPS_);
    float xn[4];
    xn[0] = (x0 - mu) * rs * __ldg(gam + l)      + __ldg(bet + l);
    xn[1] = (x1 - mu) * rs * __ldg(gam + l + 32) + __ldg(bet + l + 32);
    xn[2] = (x2 - mu) * rs * __ldg(gam + l + 64) + __ldg(bet + l + 64);
    xn[3] = (x3 - mu) * rs * __ldg(gam + l + 96) + __ldg(bet + l + 96);

    float p[H_];
    #pragma unroll
    for (int h = 0; h < H_; h++) p[h] = 0.0f;
    #pragma unroll
    for (int i = 0; i < 4; i++) {
        const int c = l + 32 * i;
        #pragma unroll
        for (int h = 0; h < H_; h++) p[h] += xn[i] * __ldg(w_z + c * H_ + h);
    }
    #pragma unroll
    for (int o = 16; o > 0; o >>= 1) {
        #pragma unroll
        for (int h = 0; h < H_; h++) p[h] += __shfl_xor_sync(0xffffffffu, p[h], o);
    }
    if (l == 0) {
        #pragma unroll
        for (int h = 0; h < H_; h++) outp[w][h] = p[h];
    }
    __syncthreads();
    if (t < 64) {
        const int h = t >> 3, j = t & 7;
        g_zb[(size_t)h * NZ_ + row0 + j] = outp[j][h];
    }
}

// ---------------- MMA GEMM with ldmatrix fragment loads ----------------
template <int FUSED>
__global__ void __launch_bounds__(256, 2) mma_gemm(
        const __nv_bfloat16* __restrict__ Ah, const __nv_bfloat16* __restrict__ Al,
        const __nv_bfloat16* __restrict__ Bth, const __nv_bfloat16* __restrict__ Btl,
        const float* __restrict__ bias, float* __restrict__ outF) {
    __shared__ __nv_bfloat16 AsH[128][40], AsL[128][40];
    __shared__ __nv_bfloat16 BsH[64][40],  BsL[64][40];
    const int t = threadIdx.x;
    const int lane = t & 31, wid = t >> 5;
    const int wm = (wid & 3) * 32;
    const int wn = (wid >> 2) * 32;
    const int row0 = blockIdx.y * 128;
    const int n0 = blockIdx.x * 64;

    float acc[2][4][4];
    #pragma unroll
    for (int a = 0; a < 2; a++)
        #pragma unroll
        for (int b = 0; b < 4; b++)
            #pragma unroll
            for (int c = 0; c < 4; c++) acc[a][b][c] = 0.0f;

    const int arow = t >> 1, aseg0 = (t & 1) * 2;
    const int bn = t >> 2, bseg = t & 3;
    const int fr = lane >> 2, fk = (lane & 3) * 2;
    // ldmatrix source coords
    const int aRowL = lane & 15;                 // row within 16-row tile
    const int aColS = (lane >> 4) * 8;           // 0 or 8
    const int bRowL = ((lane >> 4) << 3) + (lane & 7);
    const int bColS = ((lane >> 3) & 1) * 8;

    for (int kt = 0; kt < 8; kt++) {
        const int k0 = kt * 32;
        #pragma unroll
        for (int i = 0; i < 2; i++) {
            const int seg = aseg0 + i;
            *(uint4*)&AsH[arow][seg * 8] =
                *(const uint4*)(Ah + (size_t)(row0 + arow) * CM_ + k0 + seg * 8);
            *(uint4*)&AsL[arow][seg * 8] =
                *(const uint4*)(Al + (size_t)(row0 + arow) * CM_ + k0 + seg * 8);
        }
        *(uint4*)&BsH[bn][bseg * 8] =
            *(const uint4*)(Bth + (size_t)(n0 + bn) * CM_ + k0 + bseg * 8);
        *(uint4*)&BsL[bn][bseg * 8] =
            *(const uint4*)(Btl + (size_t)(n0 + bn) * CM_ + k0 + bseg * 8);
        __syncthreads();
        #pragma unroll
        for (int ks = 0; ks < 2; ks++) {
            const int kk = ks * 16;
            uint32_t aH[2][4], aL[2][4], bH[4][2], bL[4][2];
            #pragma unroll
            for (int my = 0; my < 2; my++) {
                ldsm_x4(aH[my][0], aH[my][1], aH[my][2], aH[my][3],
                        &AsH[wm + my * 16 + aRowL][kk + aColS]);
                ldsm_x4(aL[my][0], aL[my][1], aL[my][2], aL[my][3],
                        &AsL[wm + my * 16 + aRowL][kk + aColS]);
            }
            #pragma unroll
            for (int p = 0; p < 2; p++) {
                ldsm_x4(bH[2*p][0], bH[2*p][1], bH[2*p+1][0], bH[2*p+1][1],
                        &BsH[wn + p * 16 + bRowL][kk + bColS]);
                ldsm_x4(bL[2*p][0], bL[2*p][1], bL[2*p+1][0], bL[2*p+1][1],
                        &BsL[wn + p * 16 + bRowL][kk + bColS]);
            }
            #pragma unroll
            for (int my = 0; my < 2; my++)
                #pragma unroll
                for (int nx = 0; nx < 4; nx++) {
                    mma16816(acc[my][nx], aH[my], bH[nx]);
                    mma16816(acc[my][nx], aH[my], bL[nx]);
                    mma16816(acc[my][nx], aL[my], bH[nx]);
                }
        }
        __syncthreads();
    }

    const int which = FUSED ? (n0 >> 8) : 3;
    const int cbase = FUSED ? (n0 & 255) : n0;
    #pragma unroll
    for (int my = 0; my < 2; my++)
        #pragma unroll
        for (int nx = 0; nx < 4; nx++) {
            #pragma unroll
            for (int half = 0; half < 2; half++) {
                float v0 = acc[my][nx][half * 2 + 0];
                float v1 = acc[my][nx][half * 2 + 1];
                const int rr = row0 + wm + my * 16 + fr + half * 8;
                const int c = cbase + wn + nx * 8 + fk;
                if (!FUSED) {
                    float2 o2; o2.x = v0 + bias[c]; o2.y = v1 + bias[c + 1];
                    *(float2*)(outF + (size_t)rr * HC_ + c) = o2;
                } else if (which == 0) {        // q: scale, split
                    const float sc = 0.17677669529663688f;
                    v0 *= sc; v1 *= sc;
                    __nv_bfloat16 h0, l0, h1, l1;
                    bf16split(v0, h0, l0); bf16split(v1, h1, l1);
                    *(uint32_t*)&g_qh[(size_t)rr * HC_ + c] = ((uint32_t)*(uint16_t*)&h1 << 16) | *(uint16_t*)&h0;
                    *(uint32_t*)&g_ql[(size_t)rr * HC_ + c] = ((uint32_t)*(uint16_t*)&l1 << 16) | *(uint16_t*)&l0;
                } else if (which == 1) {        // k: split
                    __nv_bfloat16 h0, l0, h1, l1;
                    bf16split(v0, h0, l0); bf16split(v1, h1, l1);
                    *(uint32_t*)&g_kh[(size_t)rr * HC_ + c] = ((uint32_t)*(uint16_t*)&h1 << 16) | *(uint16_t*)&h0;
                    *(uint32_t*)&g_kl[(size_t)rr * HC_ + c] = ((uint32_t)*(uint16_t*)&l1 << 16) | *(uint16_t*)&l0;
                } else if (which == 2) {        // v: transposed split  [s][h][d][key]
                    const int key = rr & 255, sidx = rr >> 8;
                    const int hh = c >> 5, d = c & 31;
                    __nv_bfloat16 h0, l0, h1, l1;
                    bf16split(v0, h0, l0); bf16split(v1, h1, l1);
                    const size_t b0i = ((size_t)(sidx * H_ + hh) * CH_ + d) * R_ + key;
                    g_vth[b0i] = h0;       g_vtl[b0i] = l0;
                    g_vth[b0i + R_] = h1;  g_vtl[b0i + R_] = l1;   // d+1
                } else {                        // g: sigmoid -> fp32
                    float2 o2;
                    o2.x = 1.0f / (1.0f + __expf(-(v0 + bias[c])));
                    o2.y = 1.0f / (1.0f + __expf(-(v1 + bias[c + 1])));
                    *(float2*)(g_g + (size_t)rr * HC_ + c) = o2;
                }
            }
        }
}

// ---------------- kernel 4: flash-attention, smem-staged K/V + ldmatrix ----------------
// grid (H, S), 256 threads (8 warps x 32 query rows). Writes o*g bf16 hi/lo.
__global__ void __launch_bounds__(256, 1) attn_mma_kernel(const float* __restrict__ mask) {
    const int h = blockIdx.x, s = blockIdx.y;
    const int t = threadIdx.x;
    const int w = t >> 5, lane = t & 31;
    const int fr = lane >> 2, q2 = (lane & 3) * 2;
    const int bRowL = ((lane >> 4) << 3) + (lane & 7);
    const int bColS = ((lane >> 3) & 1) * 8;

    __shared__ __nv_bfloat16 KsH[32][40], KsL[32][40];
    __shared__ __nv_bfloat16 VsH[32][40], VsL[32][40];
    __shared__ float mb[256];
    mb[t] = INF_ * (mask[(size_t)s * R_ + t] - 1.0f);

    // ---- Q fragments (A operand), rows w*32 + my*16 + {fr, fr+8} ----
    uint32_t AqH[2][2][4], AqL[2][2][4];
    {
        const size_t qbase = ((size_t)(s * R_ + w * 32)) * HC_ + h * CH_;
        #pragma unroll
        for (int my = 0; my < 2; my++)
            #pragma unroll
            for (int half = 0; half < 2; half++) {
                const size_t rb = qbase + (size_t)(my * 16 + half * 8 + fr) * HC_;
                #pragma unroll
                for (int ks = 0; ks < 2; ks++) {
                    AqH[my][ks][half]     = *(const uint32_t*)(g_qh + rb + ks * 16 + q2);
                    AqH[my][ks][half + 2] = *(const uint32_t*)(g_qh + rb + ks * 16 + q2 + 8);
                    AqL[my][ks][half]     = *(const uint32_t*)(g_ql + rb + ks * 16 + q2);
                    AqL[my][ks][half + 2] = *(const uint32_t*)(g_ql + rb + ks * 16 + q2 + 8);
                }
            }
    }

    float oa[2][4][4];
    #pragma unroll
    for (int a = 0; a < 2; a++)
        #pragma unroll
        for (int b = 0; b < 4; b++)
            #pragma unroll
            for (int c = 0; c < 4; c++) oa[a][b][c] = 0.0f;
    float mrun[2][2], lrun[2][2];
    #pragma unroll
    for (int a = 0; a < 2; a++) { mrun[a][0] = mrun[a][1] = -1.0e30f; lrun[a][0] = lrun[a][1] = 0.0f; }

    const float* zb_h = g_zb + (size_t)h * NZ_;
    const __nv_bfloat16* kh_s = g_kh + ((size_t)s * R_) * HC_ + h * CH_;
    const __nv_bfloat16* kl_s = g_kl + ((size_t)s * R_) * HC_ + h * CH_;
    const __nv_bfloat16* vth_s = g_vth + (size_t)(s * H_ + h) * CH_ * R_;
    const __nv_bfloat16* vtl_s = g_vtl + (size_t)(s * H_ + h) * CH_ * R_;

    for (int jc = 0; jc < 8; jc++) {
        const int j0 = jc * 32;
        __syncthreads();   // prior chunk's ldmatrix done (also covers mb on jc=0)
        // ---- cooperative stage: K chunk (32 keys x 32 dims) + V^T chunk (32 dims x 32 keys) ----
        if (t < 128) {
            const int rr = t >> 2, cs = (t & 3) * 8;
            *(uint4*)&KsH[rr][cs] = *(const uint4*)(kh_s + (size_t)(j0 + rr) * HC_ + cs);
            *(uint4*)&KsL[rr][cs] = *(const uint4*)(kl_s + (size_t)(j0 + rr) * HC_ + cs);
        } else {
            const int t2 = t - 128;
            const int rr = t2 >> 2, cs = (t2 & 3) * 8;
            *(uint4*)&VsH[rr][cs] = *(const uint4*)(vth_s + (size_t)rr * R_ + j0 + cs);
            *(uint4*)&VsL[rr][cs] = *(const uint4*)(vtl_s + (size_t)rr * R_ + j0 + cs);
        }
        __syncthreads();

        // ---- logits init with pair bias + mask bias ----
        float la[2][4][4];
        #pragma unroll
        for (int my = 0; my < 2; my++)
            #pragma unroll
            for (int nt = 0; nt < 4; nt++)
                #pragma unroll
                for (int half = 0; half < 2; half++) {
                    const int qrow = w * 32 + my * 16 + half * 8 + fr;
                    const float2 zv = *(const float2*)(zb_h + (size_t)qrow * R_ + j0 + nt * 8 + q2);
                    la[my][nt][half * 2 + 0] = zv.x + mb[j0 + nt * 8 + q2];
                    la[my][nt][half * 2 + 1] = zv.y + mb[j0 + nt * 8 + q2 + 1];
                }
        // ---- QK^T: 3-term split, K frags via ldmatrix ----
        #pragma unroll
        for (int ks = 0; ks < 2; ks++) {
            const int kk = ks * 16;
            uint32_t bh[4][2], bl[4][2];
            #pragma unroll
            for (int p = 0; p < 2; p++) {
                ldsm_x4(bh[2*p][0], bh[2*p][1], bh[2*p+1][0], bh[2*p+1][1],
                        &KsH[p * 16 + bRowL][kk + bColS]);
                ldsm_x4(bl[2*p][0], bl[2*p][1], bl[2*p+1][0], bl[2*p+1][1],
                        &KsL[p * 16 + bRowL][kk + bColS]);
            }
            #pragma unroll
            for (int my = 0; my < 2; my++)
                #pragma unroll
                for (int nt = 0; nt < 4; nt++) {
                    mma16816(la[my][nt], AqH[my][ks], bh[nt]);
                    mma16816(la[my][nt], AqH[my][ks], bl[nt]);
                    mma16816(la[my][nt], AqL[my][ks], bh[nt]);
                }
        }
        // ---- online softmax (4 rows per thread: my x half) ----
        #pragma unroll
        for (int my = 0; my < 2; my++)
            #pragma unroll
            for (int half = 0; half < 2; half++) {
                float vmax = la[my][0][half * 2];
                #pragma unroll
                for (int nt = 0; nt < 4; nt++) {
                    vmax = fmaxf(vmax, la[my][nt][half * 2]);
                    vmax = fmaxf(vmax, la[my][nt][half * 2 + 1]);
                }
                vmax = fmaxf(vmax, __shfl_xor_sync(0xffffffffu, vmax, 1));
                vmax = fmaxf(vmax, __shfl_xor_sync(0xffffffffu, vmax, 2));
                const float mnew = fmaxf(mrun[my][half], vmax);
                const float fac = __expf(mrun[my][half] - mnew);
                mrun[my][half] = mnew;
                float rsum = 0.0f;
                #pragma unroll
                for (int nt = 0; nt < 4; nt++) {
                    float p0 = __expf(la[my][nt][half * 2] - mnew);
                    float p1 = __expf(la[my][nt][half * 2 + 1] - mnew);
                    la[my][nt][half * 2] = p0;
                    la[my][nt][half * 2 + 1] = p1;
                    rsum += p0 + p1;
                }
                rsum += __shfl_xor_sync(0xffffffffu, rsum, 1);
                rsum += __shfl_xor_sync(0xffffffffu, rsum, 2);
                lrun[my][half] = lrun[my][half] * fac + rsum;
                #pragma unroll
                for (int dt = 0; dt < 4; dt++) {
                    oa[my][dt][half * 2] *= fac;
                    oa[my][dt][half * 2 + 1] *= fac;
                }
            }
        // ---- P fragments (accumulator layout == A operand layout) ----
        uint32_t ApH[2][2][4], ApL[2][2][4];
        #pragma unroll
        for (int my = 0; my < 2; my++)
            #pragma unroll
            for (int kv = 0; kv < 2; kv++) {
                #pragma unroll
                for (int r = 0; r < 4; r++) {
                    const int nt = 2 * kv + (r >> 1);
                    const int hf = r & 1;
                    const float p0 = la[my][nt][hf * 2];
                    const float p1 = la[my][nt][hf * 2 + 1];
                    __nv_bfloat16 h0, l0, h1, l1;
                    bf16split(p0, h0, l0); bf16split(p1, h1, l1);
                    ApH[my][kv][r] = ((uint32_t)*(uint16_t*)&h1 << 16) | *(uint16_t*)&h0;
                    ApL[my][kv][r] = ((uint32_t)*(uint16_t*)&l1 << 16) | *(uint16_t*)&l0;
                }
            }
        // ---- PV: 3-term split, V frags via ldmatrix ----
        #pragma unroll
        for (int kv = 0; kv < 2; kv++) {
            uint32_t bvh[4][2], bvl[4][2];
            #pragma unroll
            for (int p = 0; p < 2; p++) {
                ldsm_x4(bvh[2*p][0], bvh[2*p][1], bvh[2*p+1][0], bvh[2*p+1][1],
                        &VsH[p * 16 + bRowL][kv * 16 + bColS]);
                ldsm_x4(bvl[2*p][0], bvl[2*p][1], bvl[2*p+1][0], bvl[2*p+1][1],
                        &VsL[p * 16 + bRowL][kv * 16 + bColS]);
            }
            #pragma unroll
            for (int my = 0; my < 2; my++)
                #pragma unroll
                for (int dt = 0; dt < 4; dt++) {
                    mma16816(oa[my][dt], ApH[my][kv], bvh[dt]);
                    mma16816(oa[my][dt], ApH[my][kv], bvl[dt]);
                    mma16816(oa[my][dt], ApL[my][kv], bvh[dt]);
                }
        }
    }
    // ---- epilogue: normalize, gate, split, store ----
    #pragma unroll
    for (int my = 0; my < 2; my++)
        #pragma unroll
        for (int half = 0; half < 2; half++) {
            const float inv = 1.0f / lrun[my][half];
            const int grow = s * R_ + w * 32 + my * 16 + half * 8 + fr;
            #pragma unroll
            for (int dt = 0; dt < 4; dt++) {
                const int dim = dt * 8 + q2;
                const float2 gf = *(const float2*)(g_g + (size_t)grow * HC_ + h * CH_ + dim);
                const float o0 = oa[my][dt][half * 2] * inv * gf.x;
                const float o1 = oa[my][dt][half * 2 + 1] * inv * gf.y;
                __nv_bfloat16 h0, l0, h1, l1;
                bf16split(o0, h0, l0); bf16split(o1, h1, l1);
                *(uint32_t*)&g_ogh[(size_t)grow * HC_ + h * CH_ + dim] =
                    ((uint32_t)*(uint16_t*)&h1 << 16) | *(uint16_t*)&h0;
                *(uint32_t*)&g_ogl[(size_t)grow * HC_ + h * CH_ + dim] =
                    ((uint32_t)*(uint16_t*)&l1 << 16) | *(uint16_t*)&l0;
            }
        }
}

// ---------------- launch ----------------
extern "C" void kernel_launch(void* const* d_in, const int* in_sizes, int n_in,
                              void* d_out, int out_size) {
    const float* m      = (const float*)d_in[0];
    const float* z      = (const float*)d_in[1];
    const float* mask   = (const float*)d_in[2];
    const float* ln_m_g = (const float*)d_in[3];
    const float* ln_m_b = (const float*)d_in[4];
    const float* ln_z_g = (const float*)d_in[5];
    const float* ln_z_b = (const float*)d_in[6];
    const float* w_z    = (const float*)d_in[7];
    const float* wq     = (const float*)d_in[8];
    const float* wk     = (const float*)d_in[9];
    const float* wv     = (const float*)d_in[10];
    const float* wg     = (const float*)d_in[11];
    const float* bg     = (const float*)d_in[12];
    const float* wo     = (const float*)d_in[13];
    const float* bo     = (const float*)d_in[14];
    float* out = (float*)d_out;

    __nv_bfloat16 *p_mh, *p_ml, *p_wth, *p_wtl, *p_woth, *p_wotl, *p_ogh, *p_ogl;
    cudaGetSymbolAddress((void**)&p_mh,   g_mh);
    cudaGetSymbolAddress((void**)&p_ml,   g_ml);
    cudaGetSymbolAddress((void**)&p_wth,  g_wth);
    cudaGetSymbolAddress((void**)&p_wtl,  g_wtl);
    cudaGetSymbolAddress((void**)&p_woth, g_woth);
    cudaGetSymbolAddress((void**)&p_wotl, g_wotl);
    cudaGetSymbolAddress((void**)&p_ogh,  g_ogh);
    cudaGetSymbolAddress((void**)&p_ogl,  g_ogl);

    ln_m_kernel<<<NROW_, 64>>>(m, ln_m_g, ln_m_b);
    wconv_all<<<dim3(CM_, 5), 256>>>(wq, wk, wv, wg, wo);
    zb_kernel<<<NZ_ / 8, 256>>>(z, ln_z_g, ln_z_b, w_z);

    mma_gemm<1><<<dim3(16, NROW_ / 128), 256>>>(p_mh, p_ml, p_wth, p_wtl, bg, nullptr);

    attn_mma_kernel<<<dim3(H_, S_), 256>>>(mask);

    mma_gemm<0><<<dim3(4, NROW_ / 128), 256>>>(p_ogh, p_ogl, p_woth, p_wotl, bo, out);
}

// round 7
// speedup vs baseline: 2.0290x; 1.1131x over previous
#include <cuda_runtime.h>
#include <cuda_bf16.h>
#include <cstdint>

// ---------------- problem constants ----------------
#define S_   128
#define R_   256
#define CM_  256
#define CZ_  128
#define H_   8
#define CH_  32
#define HC_  256
#define NROW_ (S_*R_)   // 32768
#define NZ_   (R_*R_)   // 65536
#define EPS_  1e-5f
#define INF_  1e9f

// ---------------- scratch (static device globals; no allocation) ----------------
__device__ __align__(16) __nv_bfloat16 g_mh [NROW_*CM_];   // LN(m) hi
__device__ __align__(16) __nv_bfloat16 g_ml [NROW_*CM_];   // LN(m) lo
__device__ __align__(16) __nv_bfloat16 g_wth[1024*CM_];    // [n][k] qkvg weights hi
__device__ __align__(16) __nv_bfloat16 g_wtl[1024*CM_];    // lo
__device__ __align__(16) __nv_bfloat16 g_woth[HC_*CM_];    // wo [n][k] hi
__device__ __align__(16) __nv_bfloat16 g_wotl[HC_*CM_];    // lo
__device__ __align__(16) __nv_bfloat16 g_qh [NROW_*HC_];   // q hi (scaled)
__device__ __align__(16) __nv_bfloat16 g_ql [NROW_*HC_];
__device__ __align__(16) __nv_bfloat16 g_kh [NROW_*HC_];
__device__ __align__(16) __nv_bfloat16 g_kl [NROW_*HC_];
__device__ __align__(16) __nv_bfloat16 g_vth[NROW_*HC_];   // V^T [s][h][d][key] hi
__device__ __align__(16) __nv_bfloat16 g_vtl[NROW_*HC_];
__device__ __align__(16) __nv_bfloat16 g_ogh[NROW_*HC_];   // o*g hi
__device__ __align__(16) __nv_bfloat16 g_ogl[NROW_*HC_];
__device__ float g_g  [NROW_*HC_];               // sigmoid gate (fp32)
__device__ float g_zb [H_*NZ_];                  // pair bias [H][R][R]

// ---------------- helpers ----------------
__device__ __forceinline__ void bf16split(float x, __nv_bfloat16& h, __nv_bfloat16& l) {
    h = __float2bfloat16(x);
    l = __float2bfloat16(x - __bfloat162float(h));
}
__device__ __forceinline__ void mma16816(float* d, const uint32_t* a, const uint32_t* b) {
    asm volatile(
        "mma.sync.aligned.m16n8k16.row.col.f32.bf16.bf16.f32 "
        "{%0,%1,%2,%3}, {%4,%5,%6,%7}, {%8,%9}, {%0,%1,%2,%3};\n"
        : "+f"(d[0]), "+f"(d[1]), "+f"(d[2]), "+f"(d[3])
        : "r"(a[0]), "r"(a[1]), "r"(a[2]), "r"(a[3]), "r"(b[0]), "r"(b[1]));
}
__device__ __forceinline__ void ldsm_x4(uint32_t& r0, uint32_t& r1, uint32_t& r2, uint32_t& r3,
                                        const void* p) {
    uint32_t addr = (uint32_t)__cvta_generic_to_shared(p);
    asm volatile("ldmatrix.sync.aligned.m8n8.x4.shared.b16 {%0,%1,%2,%3}, [%4];"
        : "=r"(r0), "=r"(r1), "=r"(r2), "=r"(r3) : "r"(addr));
}
__device__ __forceinline__ void cp16(void* smemp, const void* gmemp) {
    uint32_t a = (uint32_t)__cvta_generic_to_shared(smemp);
    asm volatile("cp.async.cg.shared.global [%0], [%1], 16;" :: "r"(a), "l"(gmemp));
}
__device__ __forceinline__ void cp_commit() { asm volatile("cp.async.commit_group;"); }
__device__ __forceinline__ void cp_wait1() { asm volatile("cp.async.wait_group 1;"); }
__device__ __forceinline__ void cp_wait0() { asm volatile("cp.async.wait_group 0;"); }

// ---------------- kernel 1: LayerNorm over m rows -> bf16 hi/lo planes ----------------
__global__ void ln_m_kernel(const float* __restrict__ m,
                            const float* __restrict__ gam,
                            const float* __restrict__ bet) {
    const int row = blockIdx.x;
    const int t = threadIdx.x;   // 0..63
    const float4 x = ((const float4*)(m + (size_t)row * CM_))[t];
    float s = x.x + x.y + x.z + x.w;
    float q = x.x*x.x + x.y*x.y + x.z*x.z + x.w*x.w;
    #pragma unroll
    for (int o = 16; o > 0; o >>= 1) {
        s += __shfl_down_sync(0xffffffffu, s, o);
        q += __shfl_down_sync(0xffffffffu, q, o);
    }
    __shared__ float ss[2], sq[2];
    if ((t & 31) == 0) { ss[t >> 5] = s; sq[t >> 5] = q; }
    __syncthreads();
    const float mu  = (ss[0] + ss[1]) * (1.0f / CM_);
    const float var = (sq[0] + sq[1]) * (1.0f / CM_) - mu * mu;
    const float rs  = rsqrtf(var + EPS_);
    const float4 gv = ((const float4*)gam)[t];
    const float4 bv = ((const float4*)bet)[t];
    float y[4];
    y[0] = (x.x - mu) * rs * gv.x + bv.x;
    y[1] = (x.y - mu) * rs * gv.y + bv.y;
    y[2] = (x.z - mu) * rs * gv.z + bv.z;
    y[3] = (x.w - mu) * rs * gv.w + bv.w;
    __nv_bfloat16 hv[4], lv[4];
    #pragma unroll
    for (int j = 0; j < 4; j++) bf16split(y[j], hv[j], lv[j]);
    *(uint2*)&g_mh[(size_t)row * CM_ + t * 4] = *(uint2*)hv;
    *(uint2*)&g_ml[(size_t)row * CM_ + t * 4] = *(uint2*)lv;
}

// ---------------- merged weight transpose + split ----------------
__global__ void wconv_all(const float* __restrict__ wq, const float* __restrict__ wk,
                          const float* __restrict__ wv, const float* __restrict__ wg,
                          const float* __restrict__ wo) {
    const int k = blockIdx.x, which = blockIdx.y;
    const int n = threadIdx.x;
    const float* w = (which == 0) ? wq : (which == 1) ? wk :
                     (which == 2) ? wv : (which == 3) ? wg : wo;
    const float x = w[(size_t)k * 256 + n];
    __nv_bfloat16 h, l;
    bf16split(x, h, l);
    if (which < 4) {
        g_wth[(size_t)(which * 256 + n) * CM_ + k] = h;
        g_wtl[(size_t)(which * 256 + n) * CM_ + k] = l;
    } else {
        g_woth[(size_t)n * CM_ + k] = h;
        g_wotl[(size_t)n * CM_ + k] = l;
    }
}

// ---------------- kernel 2: pair bias, one warp per z-row ----------------
__global__ void __launch_bounds__(256) zb_kernel(const float* __restrict__ z,
                          const float* __restrict__ gam,
                          const float* __restrict__ bet,
                          const float* __restrict__ w_z) {
    const int t = threadIdx.x;
    const int w = t >> 5, l = t & 31;
    const int row0 = blockIdx.x * 8;
    const int row = row0 + w;
    __shared__ float outp[8][8];

    const float* zr = z + (size_t)row * CZ_;
    float x0 = zr[l], x1 = zr[l + 32], x2 = zr[l + 64], x3 = zr[l + 96];
    float s = x0 + x1 + x2 + x3;
    float q = x0*x0 + x1*x1 + x2*x2 + x3*x3;
    #pragma unroll
    for (int o = 16; o > 0; o >>= 1) {
        s += __shfl_xor_sync(0xffffffffu, s, o);
        q += __shfl_xor_sync(0xffffffffu, q, o);
    }
    const float mu  = s * (1.0f / CZ_);
    const float var = q * (1.0f / CZ_) - mu * mu;
    const float rs  = rsqrtf(var + EPS_);
    float xn[4];
    xn[0] = (x0 - mu) * rs * __ldg(gam + l)      + __ldg(bet + l);
    xn[1] = (x1 - mu) * rs * __ldg(gam + l + 32) + __ldg(bet + l + 32);
    xn[2] = (x2 - mu) * rs * __ldg(gam + l + 64) + __ldg(bet + l + 64);
    xn[3] = (x3 - mu) * rs * __ldg(gam + l + 96) + __ldg(bet + l + 96);

    float p[H_];
    #pragma unroll
    for (int h = 0; h < H_; h++) p[h] = 0.0f;
    #pragma unroll
    for (int i = 0; i < 4; i++) {
        const int c = l + 32 * i;
        #pragma unroll
        for (int h = 0; h < H_; h++) p[h] += xn[i] * __ldg(w_z + c * H_ + h);
    }
    #pragma unroll
    for (int o = 16; o > 0; o >>= 1) {
        #pragma unroll
        for (int h = 0; h < H_; h++) p[h] += __shfl_xor_sync(0xffffffffu, p[h], o);
    }
    if (l == 0) {
        #pragma unroll
        for (int h = 0; h < H_; h++) outp[w][h] = p[h];
    }
    __syncthreads();
    if (t < 64) {
        const int h = t >> 3, j = t & 7;
        g_zb[(size_t)h * NZ_ + row0 + j] = outp[j][h];
    }
}

// ---------------- MMA GEMM: cp.async double-buffered, ldmatrix fragment loads ----------------
// dynamic smem layout (element offsets in bf16):
//   AsH [2][128][40] @ 0       AsL [2][128][40] @ 10240
//   BsH [2][64][40]  @ 20480   BsL [2][64][40]  @ 25600
#define GEMM_SMEM_BYTES ((2*128*40 + 2*128*40 + 2*64*40 + 2*64*40) * 2)
template <int FUSED>
__global__ void __launch_bounds__(256, 2) mma_gemm(
        const __nv_bfloat16* __restrict__ Ah, const __nv_bfloat16* __restrict__ Al,
        const __nv_bfloat16* __restrict__ Bth, const __nv_bfloat16* __restrict__ Btl,
        const float* __restrict__ bias, float* __restrict__ outF) {
    extern __shared__ __nv_bfloat16 smem[];
    __nv_bfloat16* AsH = smem;                    // [2][128][40]
    __nv_bfloat16* AsL = AsH + 2 * 128 * 40;
    __nv_bfloat16* BsH = AsL + 2 * 128 * 40;      // [2][64][40]
    __nv_bfloat16* BsL = BsH + 2 * 64 * 40;
    #define ASH(st,r,c) AsH[((st) * 128 + (r)) * 40 + (c)]
    #define ASL(st,r,c) AsL[((st) * 128 + (r)) * 40 + (c)]
    #define BSH(st,r,c) BsH[((st) * 64 + (r)) * 40 + (c)]
    #define BSL(st,r,c) BsL[((st) * 64 + (r)) * 40 + (c)]

    const int t = threadIdx.x;
    const int lane = t & 31, wid = t >> 5;
    const int wm = (wid & 3) * 32;
    const int wn = (wid >> 2) * 32;
    const int row0 = blockIdx.y * 128;
    const int n0 = blockIdx.x * 64;

    float acc[2][4][4];
    #pragma unroll
    for (int a = 0; a < 2; a++)
        #pragma unroll
        for (int b = 0; b < 4; b++)
            #pragma unroll
            for (int c = 0; c < 4; c++) acc[a][b][c] = 0.0f;

    const int arow = t >> 1, aseg0 = (t & 1) * 2;
    const int bn = t >> 2, bseg = t & 3;
    const int fr = lane >> 2, fk = (lane & 3) * 2;
    const int aRowL = lane & 15;
    const int aColS = (lane >> 4) * 8;
    const int bRowL = ((lane >> 4) << 3) + (lane & 7);
    const int bColS = ((lane >> 3) & 1) * 8;

    const size_t aBase = (size_t)(row0 + arow) * CM_;
    const size_t bBase = (size_t)(n0 + bn) * CM_;

    // stage issue: global -> shared via cp.async (per thread: 4x A, 2x B, 16B each)
    #define GEMM_ISSUE(st, kt) do {                                             \
        const int k0_ = (kt) * 32;                                              \
        cp16(&ASH(st, arow, aseg0 * 8),       Ah + aBase + k0_ + aseg0 * 8);    \
        cp16(&ASH(st, arow, (aseg0 + 1) * 8), Ah + aBase + k0_ + (aseg0+1)*8);  \
        cp16(&ASL(st, arow, aseg0 * 8),       Al + aBase + k0_ + aseg0 * 8);    \
        cp16(&ASL(st, arow, (aseg0 + 1) * 8), Al + aBase + k0_ + (aseg0+1)*8);  \
        cp16(&BSH(st, bn, bseg * 8),          Bth + bBase + k0_ + bseg * 8);    \
        cp16(&BSL(st, bn, bseg * 8),          Btl + bBase + k0_ + bseg * 8);    \
        cp_commit();                                                            \
    } while (0)

    GEMM_ISSUE(0, 0);
    for (int kt = 0; kt < 8; kt++) {
        const int st = kt & 1;
        if (kt < 7) { GEMM_ISSUE(st ^ 1, kt + 1); cp_wait1(); }
        else        { cp_wait0(); }
        __syncthreads();
        #pragma unroll
        for (int ks = 0; ks < 2; ks++) {
            const int kk = ks * 16;
            uint32_t aH[2][4], aL[2][4], bH[4][2], bL[4][2];
            #pragma unroll
            for (int my = 0; my < 2; my++) {
                ldsm_x4(aH[my][0], aH[my][1], aH[my][2], aH[my][3],
                        &ASH(st, wm + my * 16 + aRowL, kk + aColS));
                ldsm_x4(aL[my][0], aL[my][1], aL[my][2], aL[my][3],
                        &ASL(st, wm + my * 16 + aRowL, kk + aColS));
            }
            #pragma unroll
            for (int p = 0; p < 2; p++) {
                ldsm_x4(bH[2*p][0], bH[2*p][1], bH[2*p+1][0], bH[2*p+1][1],
                        &BSH(st, wn + p * 16 + bRowL, kk + bColS));
                ldsm_x4(bL[2*p][0], bL[2*p][1], bL[2*p+1][0], bL[2*p+1][1],
                        &BSL(st, wn + p * 16 + bRowL, kk + bColS));
            }
            #pragma unroll
            for (int my = 0; my < 2; my++)
                #pragma unroll
                for (int nx = 0; nx < 4; nx++) {
                    mma16816(acc[my][nx], aH[my], bH[nx]);
                    mma16816(acc[my][nx], aH[my], bL[nx]);
                    mma16816(acc[my][nx], aL[my], bH[nx]);
                }
        }
        __syncthreads();
    }

    const int which = FUSED ? (n0 >> 8) : 3;
    const int cbase = FUSED ? (n0 & 255) : n0;
    #pragma unroll
    for (int my = 0; my < 2; my++)
        #pragma unroll
        for (int nx = 0; nx < 4; nx++) {
            #pragma unroll
            for (int half = 0; half < 2; half++) {
                float v0 = acc[my][nx][half * 2 + 0];
                float v1 = acc[my][nx][half * 2 + 1];
                const int rr = row0 + wm + my * 16 + fr + half * 8;
                const int c = cbase + wn + nx * 8 + fk;
                if (!FUSED) {
                    float2 o2; o2.x = v0 + bias[c]; o2.y = v1 + bias[c + 1];
                    *(float2*)(outF + (size_t)rr * HC_ + c) = o2;
                } else if (which == 0) {        // q: scale, split
                    const float sc = 0.17677669529663688f;
                    v0 *= sc; v1 *= sc;
                    __nv_bfloat16 h0, l0, h1, l1;
                    bf16split(v0, h0, l0); bf16split(v1, h1, l1);
                    *(uint32_t*)&g_qh[(size_t)rr * HC_ + c] = ((uint32_t)*(uint16_t*)&h1 << 16) | *(uint16_t*)&h0;
                    *(uint32_t*)&g_ql[(size_t)rr * HC_ + c] = ((uint32_t)*(uint16_t*)&l1 << 16) | *(uint16_t*)&l0;
                } else if (which == 1) {        // k: split
                    __nv_bfloat16 h0, l0, h1, l1;
                    bf16split(v0, h0, l0); bf16split(v1, h1, l1);
                    *(uint32_t*)&g_kh[(size_t)rr * HC_ + c] = ((uint32_t)*(uint16_t*)&h1 << 16) | *(uint16_t*)&h0;
                    *(uint32_t*)&g_kl[(size_t)rr * HC_ + c] = ((uint32_t)*(uint16_t*)&l1 << 16) | *(uint16_t*)&l0;
                } else if (which == 2) {        // v: transposed split  [s][h][d][key]
                    const int key = rr & 255, sidx = rr >> 8;
                    const int hh = c >> 5, d = c & 31;
                    __nv_bfloat16 h0, l0, h1, l1;
                    bf16split(v0, h0, l0); bf16split(v1, h1, l1);
                    const size_t b0i = ((size_t)(sidx * H_ + hh) * CH_ + d) * R_ + key;
                    g_vth[b0i] = h0;       g_vtl[b0i] = l0;
                    g_vth[b0i + R_] = h1;  g_vtl[b0i + R_] = l1;   // d+1
                } else {                        // g: sigmoid -> fp32
                    float2 o2;
                    o2.x = 1.0f / (1.0f + __expf(-(v0 + bias[c])));
                    o2.y = 1.0f / (1.0f + __expf(-(v1 + bias[c + 1])));
                    *(float2*)(g_g + (size_t)rr * HC_ + c) = o2;
                }
            }
        }
    #undef ASH
    #undef ASL
    #undef BSH
    #undef BSL
    #undef GEMM_ISSUE
}

// ---------------- kernel 4: flash-attention, cp.async double-buffered K/V ----------------
__global__ void __launch_bounds__(256, 1) attn_mma_kernel(const float* __restrict__ mask) {
    const int h = blockIdx.x, s = blockIdx.y;
    const int t = threadIdx.x;
    const int w = t >> 5, lane = t & 31;
    const int fr = lane >> 2, q2 = (lane & 3) * 2;
    const int bRowL = ((lane >> 4) << 3) + (lane & 7);
    const int bColS = ((lane >> 3) & 1) * 8;

    __shared__ __nv_bfloat16 KsH[2][32][40], KsL[2][32][40];
    __shared__ __nv_bfloat16 VsH[2][32][40], VsL[2][32][40];
    __shared__ float mb[256];
    mb[t] = INF_ * (mask[(size_t)s * R_ + t] - 1.0f);

    // ---- Q fragments (A operand), rows w*32 + my*16 + {fr, fr+8} ----
    uint32_t AqH[2][2][4], AqL[2][2][4];
    {
        const size_t qbase = ((size_t)(s * R_ + w * 32)) * HC_ + h * CH_;
        #pragma unroll
        for (int my = 0; my < 2; my++)
            #pragma unroll
            for (int half = 0; half < 2; half++) {
                const size_t rb = qbase + (size_t)(my * 16 + half * 8 + fr) * HC_;
                #pragma unroll
                for (int ks = 0; ks < 2; ks++) {
                    AqH[my][ks][half]     = *(const uint32_t*)(g_qh + rb + ks * 16 + q2);
                    AqH[my][ks][half + 2] = *(const uint32_t*)(g_qh + rb + ks * 16 + q2 + 8);
                    AqL[my][ks][half]     = *(const uint32_t*)(g_ql + rb + ks * 16 + q2);
                    AqL[my][ks][half + 2] = *(const uint32_t*)(g_ql + rb + ks * 16 + q2 + 8);
                }
            }
    }

    float oa[2][4][4];
    #pragma unroll
    for (int a = 0; a < 2; a++)
        #pragma unroll
        for (int b = 0; b < 4; b++)
            #pragma unroll
            for (int c = 0; c < 4; c++) oa[a][b][c] = 0.0f;
    float mrun[2][2], lrun[2][2];
    #pragma unroll
    for (int a = 0; a < 2; a++) { mrun[a][0] = mrun[a][1] = -1.0e30f; lrun[a][0] = lrun[a][1] = 0.0f; }

    const float* zb_h = g_zb + (size_t)h * NZ_;
    const __nv_bfloat16* kh_s = g_kh + ((size_t)s * R_) * HC_ + h * CH_;
    const __nv_bfloat16* kl_s = g_kl + ((size_t)s * R_) * HC_ + h * CH_;
    const __nv_bfloat16* vth_s = g_vth + (size_t)(s * H_ + h) * CH_ * R_;
    const __nv_bfloat16* vtl_s = g_vtl + (size_t)(s * H_ + h) * CH_ * R_;

    const int srr = (t & 127) >> 2, scs = (t & 3) * 8;
    #define ATTN_ISSUE(st, jc) do {                                                      \
        const int j0_ = (jc) * 32;                                                       \
        if (t < 128) {                                                                   \
            cp16(&KsH[st][srr][scs], kh_s + (size_t)(j0_ + srr) * HC_ + scs);            \
            cp16(&KsL[st][srr][scs], kl_s + (size_t)(j0_ + srr) * HC_ + scs);            \
        } else {                                                                         \
            cp16(&VsH[st][srr][scs], vth_s + (size_t)srr * R_ + j0_ + scs);              \
            cp16(&VsL[st][srr][scs], vtl_s + (size_t)srr * R_ + j0_ + scs);              \
        }                                                                                \
        cp_commit();                                                                     \
    } while (0)

    ATTN_ISSUE(0, 0);
    for (int jc = 0; jc < 8; jc++) {
        const int j0 = jc * 32;
        const int st = jc & 1;
        if (jc < 7) { ATTN_ISSUE(st ^ 1, jc + 1); cp_wait1(); }
        else        { cp_wait0(); }
        __syncthreads();

        // ---- logits init with pair bias + mask bias ----
        float la[2][4][4];
        #pragma unroll
        for (int my = 0; my < 2; my++)
            #pragma unroll
            for (int nt = 0; nt < 4; nt++)
                #pragma unroll
                for (int half = 0; half < 2; half++) {
                    const int qrow = w * 32 + my * 16 + half * 8 + fr;
                    const float2 zv = *(const float2*)(zb_h + (size_t)qrow * R_ + j0 + nt * 8 + q2);
                    la[my][nt][half * 2 + 0] = zv.x + mb[j0 + nt * 8 + q2];
                    la[my][nt][half * 2 + 1] = zv.y + mb[j0 + nt * 8 + q2 + 1];
                }
        // ---- QK^T: 3-term split, K frags via ldmatrix ----
        #pragma unroll
        for (int ks = 0; ks < 2; ks++) {
            const int kk = ks * 16;
            uint32_t bh[4][2], bl[4][2];
            #pragma unroll
            for (int p = 0; p < 2; p++) {
                ldsm_x4(bh[2*p][0], bh[2*p][1], bh[2*p+1][0], bh[2*p+1][1],
                        &KsH[st][p * 16 + bRowL][kk + bColS]);
                ldsm_x4(bl[2*p][0], bl[2*p][1], bl[2*p+1][0], bl[2*p+1][1],
                        &KsL[st][p * 16 + bRowL][kk + bColS]);
            }
            #pragma unroll
            for (int my = 0; my < 2; my++)
                #pragma unroll
                for (int nt = 0; nt < 4; nt++) {
                    mma16816(la[my][nt], AqH[my][ks], bh[nt]);
                    mma16816(la[my][nt], AqH[my][ks], bl[nt]);
                    mma16816(la[my][nt], AqL[my][ks], bh[nt]);
                }
        }
        // ---- online softmax (4 rows per thread: my x half) ----
        #pragma unroll
        for (int my = 0; my < 2; my++)
            #pragma unroll
            for (int half = 0; half < 2; half++) {
                float vmax = la[my][0][half * 2];
                #pragma unroll
                for (int nt = 0; nt < 4; nt++) {
                    vmax = fmaxf(vmax, la[my][nt][half * 2]);
                    vmax = fmaxf(vmax, la[my][nt][half * 2 + 1]);
                }
                vmax = fmaxf(vmax, __shfl_xor_sync(0xffffffffu, vmax, 1));
                vmax = fmaxf(vmax, __shfl_xor_sync(0xffffffffu, vmax, 2));
                const float mnew = fmaxf(mrun[my][half], vmax);
                const float fac = __expf(mrun[my][half] - mnew);
                mrun[my][half] = mnew;
                float rsum = 0.0f;
                #pragma unroll
                for (int nt = 0; nt < 4; nt++) {
                    float p0 = __expf(la[my][nt][half * 2] - mnew);
                    float p1 = __expf(la[my][nt][half * 2 + 1] - mnew);
                    la[my][nt][half * 2] = p0;
                    la[my][nt][half * 2 + 1] = p1;
                    rsum += p0 + p1;
                }
                rsum += __shfl_xor_sync(0xffffffffu, rsum, 1);
                rsum += __shfl_xor_sync(0xffffffffu, rsum, 2);
                lrun[my][half] = lrun[my][half] * fac + rsum;
                #pragma unroll
                for (int dt = 0; dt < 4; dt++) {
                    oa[my][dt][half * 2] *= fac;
                    oa[my][dt][half * 2 + 1] *= fac;
                }
            }
        // ---- P fragments (accumulator layout == A operand layout) ----
        uint32_t ApH[2][2][4], ApL[2][2][4];
        #pragma unroll
        for (int my = 0; my < 2; my++)
            #pragma unroll
            for (int kv = 0; kv < 2; kv++) {
                #pragma unroll
                for (int r = 0; r < 4; r++) {
                    const int nt = 2 * kv + (r >> 1);
                    const int hf = r & 1;
                    const float p0 = la[my][nt][hf * 2];
                    const float p1 = la[my][nt][hf * 2 + 1];
                    __nv_bfloat16 h0, l0, h1, l1;
                    bf16split(p0, h0, l0); bf16split(p1, h1, l1);
                    ApH[my][kv][r] = ((uint32_t)*(uint16_t*)&h1 << 16) | *(uint16_t*)&h0;
                    ApL[my][kv][r] = ((uint32_t)*(uint16_t*)&l1 << 16) | *(uint16_t*)&l0;
                }
            }
        // ---- PV: 3-term split, V frags via ldmatrix ----
        #pragma unroll
        for (int kv = 0; kv < 2; kv++) {
            uint32_t bvh[4][2], bvl[4][2];
            #pragma unroll
            for (int p = 0; p < 2; p++) {
                ldsm_x4(bvh[2*p][0], bvh[2*p][1], bvh[2*p+1][0], bvh[2*p+1][1],
                        &VsH[st][p * 16 + bRowL][kv * 16 + bColS]);
                ldsm_x4(bvl[2*p][0], bvl[2*p][1], bvl[2*p+1][0], bvl[2*p+1][1],
                        &VsL[st][p * 16 + bRowL][kv * 16 + bColS]);
            }
            #pragma unroll
            for (int my = 0; my < 2; my++)
                #pragma unroll
                for (int dt = 0; dt < 4; dt++) {
                    mma16816(oa[my][dt], ApH[my][kv], bvh[dt]);
                    mma16816(oa[my][dt], ApH[my][kv], bvl[dt]);
                    mma16816(oa[my][dt], ApL[my][kv], bvh[dt]);
                }
        }
        __syncthreads();
    }
    // ---- epilogue: normalize, gate, split, store ----
    #pragma unroll
    for (int my = 0; my < 2; my++)
        #pragma unroll
        for (int half = 0; half < 2; half++) {
            const float inv = 1.0f / lrun[my][half];
            const int grow = s * R_ + w * 32 + my * 16 + half * 8 + fr;
            #pragma unroll
            for (int dt = 0; dt < 4; dt++) {
                const int dim = dt * 8 + q2;
                const float2 gf = *(const float2*)(g_g + (size_t)grow * HC_ + h * CH_ + dim);
                const float o0 = oa[my][dt][half * 2] * inv * gf.x;
                const float o1 = oa[my][dt][half * 2 + 1] * inv * gf.y;
                __nv_bfloat16 h0, l0, h1, l1;
                bf16split(o0, h0, l0); bf16split(o1, h1, l1);
                *(uint32_t*)&g_ogh[(size_t)grow * HC_ + h * CH_ + dim] =
                    ((uint32_t)*(uint16_t*)&h1 << 16) | *(uint16_t*)&h0;
                *(uint32_t*)&g_ogl[(size_t)grow * HC_ + h * CH_ + dim] =
                    ((uint32_t)*(uint16_t*)&l1 << 16) | *(uint16_t*)&l0;
            }
        }
    #undef ATTN_ISSUE
}

// ---------------- launch ----------------
extern "C" void kernel_launch(void* const* d_in, const int* in_sizes, int n_in,
                              void* d_out, int out_size) {
    const float* m      = (const float*)d_in[0];
    const float* z      = (const float*)d_in[1];
    const float* mask   = (const float*)d_in[2];
    const float* ln_m_g = (const float*)d_in[3];
    const float* ln_m_b = (const float*)d_in[4];
    const float* ln_z_g = (const float*)d_in[5];
    const float* ln_z_b = (const float*)d_in[6];
    const float* w_z    = (const float*)d_in[7];
    const float* wq     = (const float*)d_in[8];
    const float* wk     = (const float*)d_in[9];
    const float* wv     = (const float*)d_in[10];
    const float* wg     = (const float*)d_in[11];
    const float* bg     = (const float*)d_in[12];
    const float* wo     = (const float*)d_in[13];
    const float* bo     = (const float*)d_in[14];
    float* out = (float*)d_out;

    __nv_bfloat16 *p_mh, *p_ml, *p_wth, *p_wtl, *p_woth, *p_wotl, *p_ogh, *p_ogl;
    cudaGetSymbolAddress((void**)&p_mh,   g_mh);
    cudaGetSymbolAddress((void**)&p_ml,   g_ml);
    cudaGetSymbolAddress((void**)&p_wth,  g_wth);
    cudaGetSymbolAddress((void**)&p_wtl,  g_wtl);
    cudaGetSymbolAddress((void**)&p_woth, g_woth);
    cudaGetSymbolAddress((void**)&p_wotl, g_wotl);
    cudaGetSymbolAddress((void**)&p_ogh,  g_ogh);
    cudaGetSymbolAddress((void**)&p_ogl,  g_ogl);

    static bool attrs_set = false;
    if (!attrs_set) {
        cudaFuncSetAttribute(mma_gemm<1>, cudaFuncAttributeMaxDynamicSharedMemorySize, GEMM_SMEM_BYTES);
        cudaFuncSetAttribute(mma_gemm<0>, cudaFuncAttributeMaxDynamicSharedMemorySize, GEMM_SMEM_BYTES);
        attrs_set = true;
    }

    ln_m_kernel<<<NROW_, 64>>>(m, ln_m_g, ln_m_b);
    wconv_all<<<dim3(CM_, 5), 256>>>(wq, wk, wv, wg, wo);
    zb_kernel<<<NZ_ / 8, 256>>>(z, ln_z_g, ln_z_b, w_z);

    mma_gemm<1><<<dim3(16, NROW_ / 128), 256, GEMM_SMEM_BYTES>>>(p_mh, p_ml, p_wth, p_wtl, bg, nullptr);

    attn_mma_kernel<<<dim3(H_, S_), 256>>>(mask);

    mma_gemm<0><<<dim3(4, NROW_ / 128), 256, GEMM_SMEM_BYTES>>>(p_ogh, p_ogl, p_woth, p_wotl, bo, out);
}